// round 1
// baseline (speedup 1.0000x reference)
#include <cuda_runtime.h>
#include <cuda_bf16.h>

#define NNODES 100000
#define FEAT   128
#define NEDGES 1600000
#define ETOT   (NEDGES + NNODES)
#define BN_EPS 1e-5f
#define NEG_SLOPE 0.2f

// ---------------- static device scratch (no allocations allowed) ----------------
__device__ float g_h[(size_t)NNODES * FEAT];     // h = x @ W^T for current layer
__device__ float g_acc[(size_t)NNODES * FEAT];   // layer output / next layer input
__device__ float g_as[NNODES];                   // alpha_src per node
__device__ float g_ad[NNODES];                   // alpha_dst per node
__device__ int   g_cnt[NNODES];
__device__ int   g_rowptr[NNODES + 1];
__device__ int   g_off[NNODES];
__device__ int   g_csrc[ETOT];                   // CSR by dst: src node ids
__device__ float g_bnsum[FEAT];
__device__ float g_bnsq[FEAT];

// ---------------- CSR build ----------------
__global__ void init_cnt_kernel() {
    int i = blockIdx.x * blockDim.x + threadIdx.x;
    if (i < NNODES) g_cnt[i] = 1;   // self loop
}

__global__ void count_kernel(const int* __restrict__ ei) {
    int e = blockIdx.x * blockDim.x + threadIdx.x;
    if (e < NEDGES) atomicAdd(&g_cnt[ei[NEDGES + e]], 1);
}

// single-block scan over g_cnt -> exclusive prefix in g_rowptr
__global__ void scan_kernel() {
    __shared__ int s[1024];
    __shared__ int carry_s;
    int tid = threadIdx.x;
    if (tid == 0) { carry_s = 0; g_rowptr[0] = 0; }
    __syncthreads();
    for (int base = 0; base < NNODES; base += 1024) {
        int v = (base + tid < NNODES) ? g_cnt[base + tid] : 0;
        s[tid] = v;
        __syncthreads();
        for (int off = 1; off < 1024; off <<= 1) {
            int t = (tid >= off) ? s[tid - off] : 0;
            __syncthreads();
            s[tid] += t;
            __syncthreads();
        }
        if (base + tid < NNODES) g_rowptr[base + tid + 1] = carry_s + s[tid];
        __syncthreads();
        if (tid == 0) carry_s += s[1023];
        __syncthreads();
    }
}

__global__ void copy_off_kernel() {
    int i = blockIdx.x * blockDim.x + threadIdx.x;
    if (i < NNODES) g_off[i] = g_rowptr[i];
}

__global__ void scatter_kernel(const int* __restrict__ ei) {
    int idx = blockIdx.x * blockDim.x + threadIdx.x;
    if (idx >= ETOT) return;
    int s, d;
    if (idx < NEDGES) { s = ei[idx]; d = ei[NEDGES + idx]; }
    else { s = d = idx - NEDGES; }
    int p = atomicAdd(&g_off[d], 1);
    g_csrc[p] = s;
}

// ---------------- GEMM: g_h = X @ W^T  (X: [M,128], W: [128,128] row-major) ----------------
__global__ __launch_bounds__(256) void gemm_kernel(const float* __restrict__ X,
                                                   const float* __restrict__ W, int M) {
    __shared__ float Xs[64][16];
    __shared__ float Ws[16][128];
    int tid = threadIdx.x;
    int bm = blockIdx.x * 64;
    int tx = tid & 15, ty = tid >> 4;

    float acc[4][8];
#pragma unroll
    for (int i = 0; i < 4; i++)
#pragma unroll
        for (int j = 0; j < 8; j++) acc[i][j] = 0.f;

    int xr = tid >> 2;            // 0..63
    int xc = (tid & 3) * 4;       // 0,4,8,12
    int wo = tid >> 1;            // 0..127
    int wh = (tid & 1) * 8;       // 0 or 8

    for (int k0 = 0; k0 < FEAT; k0 += 16) {
        float4 xv = make_float4(0.f, 0.f, 0.f, 0.f);
        if (bm + xr < M) xv = *(const float4*)&X[(size_t)(bm + xr) * FEAT + k0 + xc];
        *(float4*)&Xs[xr][xc] = xv;

        float4 w0 = *(const float4*)&W[(size_t)wo * FEAT + k0 + wh];
        float4 w1 = *(const float4*)&W[(size_t)wo * FEAT + k0 + wh + 4];
        Ws[wh + 0][wo] = w0.x; Ws[wh + 1][wo] = w0.y;
        Ws[wh + 2][wo] = w0.z; Ws[wh + 3][wo] = w0.w;
        Ws[wh + 4][wo] = w1.x; Ws[wh + 5][wo] = w1.y;
        Ws[wh + 6][wo] = w1.z; Ws[wh + 7][wo] = w1.w;
        __syncthreads();

#pragma unroll
        for (int kk = 0; kk < 16; kk++) {
            float a0 = Xs[ty * 4 + 0][kk];
            float a1 = Xs[ty * 4 + 1][kk];
            float a2 = Xs[ty * 4 + 2][kk];
            float a3 = Xs[ty * 4 + 3][kk];
            float4 b0 = *(float4*)&Ws[kk][tx * 8];
            float4 b1 = *(float4*)&Ws[kk][tx * 8 + 4];
            float b[8] = {b0.x, b0.y, b0.z, b0.w, b1.x, b1.y, b1.z, b1.w};
            float a[4] = {a0, a1, a2, a3};
#pragma unroll
            for (int i = 0; i < 4; i++)
#pragma unroll
                for (int j = 0; j < 8; j++) acc[i][j] += a[i] * b[j];
        }
        __syncthreads();
    }

#pragma unroll
    for (int i = 0; i < 4; i++) {
        int r = bm + ty * 4 + i;
        if (r < M) {
            float4 o0 = make_float4(acc[i][0], acc[i][1], acc[i][2], acc[i][3]);
            float4 o1 = make_float4(acc[i][4], acc[i][5], acc[i][6], acc[i][7]);
            *(float4*)&g_h[(size_t)r * FEAT + tx * 8] = o0;
            *(float4*)&g_h[(size_t)r * FEAT + tx * 8 + 4] = o1;
        }
    }
}

// ---------------- alpha_s / alpha_d per node (warp per node) ----------------
__global__ __launch_bounds__(256) void alpha_kernel(const float* __restrict__ asrc,
                                                    const float* __restrict__ adst) {
    int gt = blockIdx.x * blockDim.x + threadIdx.x;
    int w = gt >> 5, lane = gt & 31;
    if (w >= NNODES) return;
    float4 v  = ((const float4*)g_h)[(size_t)w * 32 + lane];
    float4 s4 = ((const float4*)asrc)[lane];
    float4 d4 = ((const float4*)adst)[lane];
    float s = v.x * s4.x + v.y * s4.y + v.z * s4.z + v.w * s4.w;
    float d = v.x * d4.x + v.y * d4.y + v.z * d4.z + v.w * d4.w;
#pragma unroll
    for (int o = 16; o; o >>= 1) {
        s += __shfl_xor_sync(0xffffffffu, s, o);
        d += __shfl_xor_sync(0xffffffffu, d, o);
    }
    if (lane == 0) { g_as[w] = s; g_ad[w] = d; }
}

__device__ __forceinline__ float leaky(float x) {
    return x >= 0.f ? x : NEG_SLOPE * x;
}

// ---------------- edge softmax + aggregation: warp per destination ----------------
__global__ __launch_bounds__(256) void edge_kernel(const float* __restrict__ bias,
                                                   float* __restrict__ out) {
    int gt = blockIdx.x * blockDim.x + threadIdx.x;
    int d = gt >> 5, lane = gt & 31;
    if (d >= NNODES) return;
    int beg = g_rowptr[d], end = g_rowptr[d + 1];
    float ad = g_ad[d];

    // pass 1: max
    float m = -1e30f;
    for (int i = beg + lane; i < end; i += 32) {
        float e = leaky(g_as[g_csrc[i]] + ad);
        m = fmaxf(m, e);
    }
#pragma unroll
    for (int o = 16; o; o >>= 1) m = fmaxf(m, __shfl_xor_sync(0xffffffffu, m, o));

    // pass 2: denom
    float sum = 0.f;
    for (int i = beg + lane; i < end; i += 32) {
        float e = leaky(g_as[g_csrc[i]] + ad);
        sum += __expf(e - m);
    }
#pragma unroll
    for (int o = 16; o; o >>= 1) sum += __shfl_xor_sync(0xffffffffu, sum, o);
    float inv = 1.f / sum;

    // pass 3: weighted gather-accumulate (all lanes walk edges together)
    float ax = 0.f, ay = 0.f, az = 0.f, aw = 0.f;
    const float4* h4 = (const float4*)g_h;
#pragma unroll 2
    for (int i = beg; i < end; i++) {
        int s = g_csrc[i];                       // broadcast load
        float e = leaky(g_as[s] + ad);
        float w = __expf(e - m) * inv;
        float4 v = h4[(size_t)s * 32 + lane];    // coalesced 512B per edge
        ax += w * v.x; ay += w * v.y; az += w * v.z; aw += w * v.w;
    }
    float4 bb = ((const float4*)bias)[lane];
    float4 o = make_float4(ax + bb.x, ay + bb.y, az + bb.z, aw + bb.w);
    ((float4*)out)[(size_t)d * 32 + lane] = o;
}

// ---------------- batch norm + relu ----------------
__global__ void bn_zero_kernel() {
    int f = threadIdx.x;
    if (f < FEAT) { g_bnsum[f] = 0.f; g_bnsq[f] = 0.f; }
}

__global__ __launch_bounds__(128) void bn_reduce_kernel() {
    int f = threadIdx.x;
    int r0 = blockIdx.x * 500;
    float s = 0.f, s2 = 0.f;
    for (int r = 0; r < 500; r++) {
        int row = r0 + r;
        if (row < NNODES) {
            float v = g_acc[(size_t)row * FEAT + f];
            s += v; s2 += v * v;
        }
    }
    atomicAdd(&g_bnsum[f], s);
    atomicAdd(&g_bnsq[f], s2);
}

__global__ __launch_bounds__(256) void bn_apply_kernel(const float* __restrict__ gamma,
                                                       const float* __restrict__ beta) {
    int i = blockIdx.x * blockDim.x + threadIdx.x;
    if (i >= NNODES * 32) return;
    float4 v = ((float4*)g_acc)[i];
    int f = (i & 31) * 4;
    const float invN = 1.f / (float)NNODES;
    float r[4] = {v.x, v.y, v.z, v.w};
#pragma unroll
    for (int j = 0; j < 4; j++) {
        float mu = g_bnsum[f + j] * invN;
        float var = g_bnsq[f + j] * invN - mu * mu;
        float y = gamma[f + j] * (r[j] - mu) * rsqrtf(var + BN_EPS) + beta[f + j];
        r[j] = fmaxf(y, 0.f);
    }
    ((float4*)g_acc)[i] = make_float4(r[0], r[1], r[2], r[3]);
}

// ---------------- launch ----------------
extern "C" void kernel_launch(void* const* d_in, const int* in_sizes, int n_in,
                              void* d_out, int out_size) {
    const float* x  = (const float*)d_in[0];
    const int*   ei = (const int*)d_in[1];
    const float* W[3]  = {(const float*)d_in[2], (const float*)d_in[6],  (const float*)d_in[10]};
    const float* As[3] = {(const float*)d_in[3], (const float*)d_in[7],  (const float*)d_in[11]};
    const float* Ad[3] = {(const float*)d_in[4], (const float*)d_in[8],  (const float*)d_in[12]};
    const float* B[3]  = {(const float*)d_in[5], (const float*)d_in[9],  (const float*)d_in[13]};
    const float* gam[2] = {(const float*)d_in[14], (const float*)d_in[16]};
    const float* bet[2] = {(const float*)d_in[15], (const float*)d_in[17]};

    float* acc_ptr = nullptr;
    cudaGetSymbolAddress((void**)&acc_ptr, g_acc);

    // CSR build (by destination, self-loops included)
    init_cnt_kernel<<<(NNODES + 255) / 256, 256>>>();
    count_kernel<<<(NEDGES + 255) / 256, 256>>>(ei);
    scan_kernel<<<1, 1024>>>();
    copy_off_kernel<<<(NNODES + 255) / 256, 256>>>();
    scatter_kernel<<<(ETOT + 255) / 256, 256>>>(ei);

    const float* cur = x;
    const int warp_grid = (NNODES * 32 + 255) / 256;  // 12500
    for (int l = 0; l < 3; l++) {
        gemm_kernel<<<(NNODES + 63) / 64, 256>>>(cur, W[l], NNODES);
        alpha_kernel<<<warp_grid, 256>>>(As[l], Ad[l]);
        float* outp = (l == 2) ? (float*)d_out : acc_ptr;
        edge_kernel<<<warp_grid, 256>>>(B[l], outp);
        if (l < 2) {
            bn_zero_kernel<<<1, 128>>>();
            bn_reduce_kernel<<<200, 128>>>();
            bn_apply_kernel<<<warp_grid, 256>>>(gam[l], bet[l]);
            cur = acc_ptr;
        }
    }
}

// round 2
// speedup vs baseline: 1.2243x; 1.2243x over previous
#include <cuda_runtime.h>
#include <cuda_fp16.h>

#define NNODES 100000
#define FEAT   128
#define NEDGES 1600000
#define ETOT   (NEDGES + NNODES)
#define BN_EPS 1e-5f
#define NEG_SLOPE 0.2f

// ---------------- static device scratch ----------------
__device__ __half g_hh[(size_t)NNODES * FEAT];   // h in fp16 (gather payload)
__device__ float  g_acc[(size_t)NNODES * FEAT];  // layer output / next input (fp32)
__device__ float  g_as[NNODES];
__device__ float  g_ad[NNODES];
__device__ int    g_cnt[NNODES];
__device__ int    g_rowptr[NNODES + 1];
__device__ int    g_off[NNODES];
__device__ int    g_csrc[ETOT];
__device__ float  g_bnsum0[FEAT], g_bnsq0[FEAT];
__device__ float  g_bnsum1[FEAT], g_bnsq1[FEAT];

// ---------------- CSR build ----------------
__global__ void init_kernel() {
    int i = blockIdx.x * blockDim.x + threadIdx.x;
    if (i < NNODES) g_cnt[i] = 1;   // self loop
    if (i < FEAT) {
        g_bnsum0[i] = 0.f; g_bnsq0[i] = 0.f;
        g_bnsum1[i] = 0.f; g_bnsq1[i] = 0.f;
    }
}

__global__ void count_kernel(const int* __restrict__ ei) {
    int e = blockIdx.x * blockDim.x + threadIdx.x;
    if (e < NEDGES) atomicAdd(&g_cnt[ei[NEDGES + e]], 1);
}

// single-block shuffle scan -> rowptr (inclusive shifted) and off (exclusive)
__global__ void scan_kernel() {
    __shared__ int wsum[32];
    __shared__ int carry_s;
    int tid = threadIdx.x, lane = tid & 31, wid = tid >> 5;
    if (tid == 0) { carry_s = 0; g_rowptr[0] = 0; }
    __syncthreads();
    for (int base = 0; base < NNODES; base += 1024) {
        int i = base + tid;
        int v = (i < NNODES) ? g_cnt[i] : 0;
        int s = v;
#pragma unroll
        for (int o = 1; o < 32; o <<= 1) {
            int t = __shfl_up_sync(0xffffffffu, s, o);
            if (lane >= o) s += t;
        }
        if (lane == 31) wsum[wid] = s;
        __syncthreads();
        if (wid == 0) {
            int ws = wsum[lane];
#pragma unroll
            for (int o = 1; o < 32; o <<= 1) {
                int t = __shfl_up_sync(0xffffffffu, ws, o);
                if (lane >= o) ws += t;
            }
            wsum[lane] = ws;
        }
        __syncthreads();
        int incl = s + (wid ? wsum[wid - 1] : 0) + carry_s;
        if (i < NNODES) {
            g_rowptr[i + 1] = incl;
            g_off[i] = incl - v;
        }
        __syncthreads();
        if (tid == 1023) carry_s = incl;
        __syncthreads();
    }
}

__global__ void scatter_kernel(const int* __restrict__ ei) {
    int idx = blockIdx.x * blockDim.x + threadIdx.x;
    if (idx >= ETOT) return;
    int s, d;
    if (idx < NEDGES) { s = ei[idx]; d = ei[NEDGES + idx]; }
    else { s = d = idx - NEDGES; }
    int p = atomicAdd(&g_off[d], 1);
    g_csrc[p] = s;
}

// ---------------- GEMM + fused BN-on-load + alpha epilogue ----------------
// g_hh = (bn?) relu(bn(X)) @ W^T ; g_as/g_ad = h . a_src / a_dst
__global__ __launch_bounds__(256) void gemm_kernel(
    const float* __restrict__ X, const float* __restrict__ W,
    const float* __restrict__ asrc, const float* __restrict__ adst,
    const float* __restrict__ gamma, const float* __restrict__ beta,
    const float* __restrict__ bsum, const float* __restrict__ bsq,
    int use_bn, int M) {
    __shared__ float Xs[64][16];
    __shared__ float Ws[16][128];
    __shared__ float sc[FEAT], sh[FEAT];
    int tid = threadIdx.x;
    int bm = blockIdx.x * 64;
    int tx = tid & 15, ty = tid >> 4;

    if (tid < FEAT) {
        if (use_bn) {
            const float invN = 1.f / (float)NNODES;
            float mu = bsum[tid] * invN;
            float var = bsq[tid] * invN - mu * mu;
            float s = gamma[tid] * rsqrtf(var + BN_EPS);
            sc[tid] = s;
            sh[tid] = beta[tid] - mu * s;
        } else { sc[tid] = 1.f; sh[tid] = 0.f; }
    }

    float acc[4][8];
#pragma unroll
    for (int i = 0; i < 4; i++)
#pragma unroll
        for (int j = 0; j < 8; j++) acc[i][j] = 0.f;

    int xr = tid >> 2;
    int xc = (tid & 3) * 4;
    int wo = tid >> 1;
    int wh = (tid & 1) * 8;
    __syncthreads();

    for (int k0 = 0; k0 < FEAT; k0 += 16) {
        float4 xv = make_float4(0.f, 0.f, 0.f, 0.f);
        if (bm + xr < M) xv = *(const float4*)&X[(size_t)(bm + xr) * FEAT + k0 + xc];
        {
            int c = k0 + xc;
            float y0 = xv.x * sc[c + 0] + sh[c + 0];
            float y1 = xv.y * sc[c + 1] + sh[c + 1];
            float y2 = xv.z * sc[c + 2] + sh[c + 2];
            float y3 = xv.w * sc[c + 3] + sh[c + 3];
            if (use_bn) { y0 = fmaxf(y0, 0.f); y1 = fmaxf(y1, 0.f); y2 = fmaxf(y2, 0.f); y3 = fmaxf(y3, 0.f); }
            *(float4*)&Xs[xr][xc] = make_float4(y0, y1, y2, y3);
        }

        float4 w0 = *(const float4*)&W[(size_t)wo * FEAT + k0 + wh];
        float4 w1 = *(const float4*)&W[(size_t)wo * FEAT + k0 + wh + 4];
        Ws[wh + 0][wo] = w0.x; Ws[wh + 1][wo] = w0.y;
        Ws[wh + 2][wo] = w0.z; Ws[wh + 3][wo] = w0.w;
        Ws[wh + 4][wo] = w1.x; Ws[wh + 5][wo] = w1.y;
        Ws[wh + 6][wo] = w1.z; Ws[wh + 7][wo] = w1.w;
        __syncthreads();

#pragma unroll
        for (int kk = 0; kk < 16; kk++) {
            float a[4] = {Xs[ty * 4 + 0][kk], Xs[ty * 4 + 1][kk],
                          Xs[ty * 4 + 2][kk], Xs[ty * 4 + 3][kk]};
            float4 b0 = *(float4*)&Ws[kk][tx * 8];
            float4 b1 = *(float4*)&Ws[kk][tx * 8 + 4];
            float b[8] = {b0.x, b0.y, b0.z, b0.w, b1.x, b1.y, b1.z, b1.w};
#pragma unroll
            for (int i = 0; i < 4; i++)
#pragma unroll
                for (int j = 0; j < 8; j++) acc[i][j] += a[i] * b[j];
        }
        __syncthreads();
    }

    // alpha weights for this thread's 8 columns
    float4 s0 = ((const float4*)asrc)[tx * 2];
    float4 s1 = ((const float4*)asrc)[tx * 2 + 1];
    float4 d0 = ((const float4*)adst)[tx * 2];
    float4 d1 = ((const float4*)adst)[tx * 2 + 1];
    float av[8] = {s0.x, s0.y, s0.z, s0.w, s1.x, s1.y, s1.z, s1.w};
    float dv[8] = {d0.x, d0.y, d0.z, d0.w, d1.x, d1.y, d1.z, d1.w};

#pragma unroll
    for (int i = 0; i < 4; i++) {
        int r = bm + ty * 4 + i;
        float ps = 0.f, pd = 0.f;
#pragma unroll
        for (int j = 0; j < 8; j++) { ps += acc[i][j] * av[j]; pd += acc[i][j] * dv[j]; }
#pragma unroll
        for (int o = 8; o; o >>= 1) {
            ps += __shfl_xor_sync(0xffffffffu, ps, o);
            pd += __shfl_xor_sync(0xffffffffu, pd, o);
        }
        if (r < M) {
            // fp16 h store (8 halves = 16B)
            __half2 hh[4];
            hh[0] = __floats2half2_rn(acc[i][0], acc[i][1]);
            hh[1] = __floats2half2_rn(acc[i][2], acc[i][3]);
            hh[2] = __floats2half2_rn(acc[i][4], acc[i][5]);
            hh[3] = __floats2half2_rn(acc[i][6], acc[i][7]);
            *(uint4*)&g_hh[(size_t)r * FEAT + tx * 8] = *(uint4*)hh;
            if (tx == 0) { g_as[r] = ps; g_ad[r] = pd; }
        }
    }
}

__device__ __forceinline__ float leaky(float x) {
    return x >= 0.f ? x : NEG_SLOPE * x;
}

// ---------------- edge softmax + aggregation (warp per dst) + BN-stat epilogue ----------------
__global__ __launch_bounds__(256) void edge_kernel(const float* __restrict__ bias,
                                                   float* __restrict__ out,
                                                   float* __restrict__ bnsum,
                                                   float* __restrict__ bnsq,
                                                   int do_bn) {
    __shared__ float  ew[8][64];
    __shared__ float4 psum[8][32];
    __shared__ float4 psq[8][32];
    int tid = threadIdx.x, w = tid >> 5, lane = tid & 31;
    int d = blockIdx.x * 8 + w;            // grid = 12500 exactly -> always valid
    int beg = g_rowptr[d], end = g_rowptr[d + 1];
    int deg = end - beg;
    float ad = g_ad[d];
    float m, inv;
    bool cached = (deg <= 64);

    if (cached) {
        float e0 = -1e30f, e1 = -1e30f;
        if (lane < deg)      e0 = leaky(g_as[g_csrc[beg + lane]] + ad);
        if (32 + lane < deg) e1 = leaky(g_as[g_csrc[beg + 32 + lane]] + ad);
        m = fmaxf(e0, e1);
#pragma unroll
        for (int o = 16; o; o >>= 1) m = fmaxf(m, __shfl_xor_sync(0xffffffffu, m, o));
        float x0 = (lane < deg)      ? __expf(e0 - m) : 0.f;
        float x1 = (32 + lane < deg) ? __expf(e1 - m) : 0.f;
        ew[w][lane] = x0; ew[w][lane + 32] = x1;
        float sum = x0 + x1;
#pragma unroll
        for (int o = 16; o; o >>= 1) sum += __shfl_xor_sync(0xffffffffu, sum, o);
        inv = 1.f / sum;
        __syncwarp();
    } else {
        m = -1e30f;
        for (int i = beg + lane; i < end; i += 32)
            m = fmaxf(m, leaky(g_as[g_csrc[i]] + ad));
#pragma unroll
        for (int o = 16; o; o >>= 1) m = fmaxf(m, __shfl_xor_sync(0xffffffffu, m, o));
        float sum = 0.f;
        for (int i = beg + lane; i < end; i += 32)
            sum += __expf(leaky(g_as[g_csrc[i]] + ad) - m);
#pragma unroll
        for (int o = 16; o; o >>= 1) sum += __shfl_xor_sync(0xffffffffu, sum, o);
        inv = 1.f / sum;
    }

    float ax = 0.f, ay = 0.f, az = 0.f, aw = 0.f;
    const uint2* h2 = (const uint2*)g_hh;
#pragma unroll 2
    for (int i = 0; i < deg; i++) {
        int s = g_csrc[beg + i];
        float wt = cached ? ew[w][i] * inv
                          : __expf(leaky(g_as[s] + ad) - m) * inv;
        uint2 raw = h2[(size_t)s * 32 + lane];   // 8B/lane = 256B/edge
        float2 f0 = __half22float2(*(__half2*)&raw.x);
        float2 f1 = __half22float2(*(__half2*)&raw.y);
        ax += wt * f0.x; ay += wt * f0.y; az += wt * f1.x; aw += wt * f1.y;
    }
    float4 bb = ((const float4*)bias)[lane];
    float4 o = make_float4(ax + bb.x, ay + bb.y, az + bb.z, aw + bb.w);
    ((float4*)out)[(size_t)d * 32 + lane] = o;

    if (do_bn) {
        psum[w][lane] = o;
        psq[w][lane]  = make_float4(o.x * o.x, o.y * o.y, o.z * o.z, o.w * o.w);
        __syncthreads();
        if (tid < FEAT) {
            float s = 0.f, q = 0.f;
            const float* ps = (const float*)psum;
            const float* pq = (const float*)psq;
#pragma unroll
            for (int ww = 0; ww < 8; ww++) {
                s += ps[ww * 128 + tid];
                q += pq[ww * 128 + tid];
            }
            atomicAdd(&bnsum[tid], s);
            atomicAdd(&bnsq[tid], q);
        }
    }
}

// ---------------- launch ----------------
extern "C" void kernel_launch(void* const* d_in, const int* in_sizes, int n_in,
                              void* d_out, int out_size) {
    const float* x  = (const float*)d_in[0];
    const int*   ei = (const int*)d_in[1];
    const float* W[3]  = {(const float*)d_in[2], (const float*)d_in[6],  (const float*)d_in[10]};
    const float* As[3] = {(const float*)d_in[3], (const float*)d_in[7],  (const float*)d_in[11]};
    const float* Ad[3] = {(const float*)d_in[4], (const float*)d_in[8],  (const float*)d_in[12]};
    const float* B[3]  = {(const float*)d_in[5], (const float*)d_in[9],  (const float*)d_in[13]};
    const float* gam[2] = {(const float*)d_in[14], (const float*)d_in[16]};
    const float* bet[2] = {(const float*)d_in[15], (const float*)d_in[17]};

    float *acc_ptr, *bs0, *bq0, *bs1, *bq1;
    cudaGetSymbolAddress((void**)&acc_ptr, g_acc);
    cudaGetSymbolAddress((void**)&bs0, g_bnsum0);
    cudaGetSymbolAddress((void**)&bq0, g_bnsq0);
    cudaGetSymbolAddress((void**)&bs1, g_bnsum1);
    cudaGetSymbolAddress((void**)&bq1, g_bnsq1);

    // CSR build: launches 1-4 (GEMM lands at launch 5 for ncu -s 5)
    init_kernel<<<(NNODES + 255) / 256, 256>>>();
    count_kernel<<<(NEDGES + 255) / 256, 256>>>(ei);
    scan_kernel<<<1, 1024>>>();
    scatter_kernel<<<(ETOT + 255) / 256, 256>>>(ei);

    const int gemm_grid = (NNODES + 63) / 64;
    const int edge_grid = NNODES / 8;   // 12500, exact

    // layer 0
    gemm_kernel<<<gemm_grid, 256>>>(x, W[0], As[0], Ad[0],
                                    nullptr, nullptr, nullptr, nullptr, 0, NNODES);
    edge_kernel<<<edge_grid, 256>>>(B[0], acc_ptr, bs0, bq0, 1);
    // layer 1 (BN0+relu fused into X load)
    gemm_kernel<<<gemm_grid, 256>>>(acc_ptr, W[1], As[1], Ad[1],
                                    gam[0], bet[0], bs0, bq0, 1, NNODES);
    edge_kernel<<<edge_grid, 256>>>(B[1], acc_ptr, bs1, bq1, 1);
    // layer 2 (BN1+relu fused into X load)
    gemm_kernel<<<gemm_grid, 256>>>(acc_ptr, W[2], As[2], Ad[2],
                                    gam[1], bet[1], bs1, bq1, 1, NNODES);
    edge_kernel<<<edge_grid, 256>>>(B[2], (float*)d_out, nullptr, nullptr, 0);
}

// round 4
// speedup vs baseline: 1.8201x; 1.4867x over previous
#include <cuda_runtime.h>
#include <cuda_fp16.h>
#include <cstdint>

#define NNODES 100000
#define FEAT   128
#define NEDGES 1600000
#define ETOT   (NEDGES + NNODES)
#define BN_EPS 1e-5f
#define NEG_SLOPE 0.2f
#define LDX    136   // padded smem row pitch in halves (272B: conflict-free ldmatrix)

// ---------------- static device scratch ----------------
__device__ __half g_hh[(size_t)NNODES * FEAT];   // h in fp16 (gather payload)
__device__ float  g_acc[(size_t)NNODES * FEAT];  // layer output / next input (fp32)
__device__ __half g_Wh[3][FEAT * FEAT];          // fp16 weights
__device__ float  g_as[NNODES];
__device__ float  g_ad[NNODES];
__device__ int    g_cnt[NNODES];
__device__ int    g_rowptr[NNODES + 1];
__device__ int    g_off[NNODES];
__device__ int    g_csrc[ETOT];
__device__ float  g_bnsum0[FEAT], g_bnsq0[FEAT];
__device__ float  g_bnsum1[FEAT], g_bnsq1[FEAT];

// ---------------- init + weight convert ----------------
__global__ void init_kernel() {
    int i = blockIdx.x * blockDim.x + threadIdx.x;
    if (i < NNODES) g_cnt[i] = 1;   // self loop
    if (i < FEAT) {
        g_bnsum0[i] = 0.f; g_bnsq0[i] = 0.f;
        g_bnsum1[i] = 0.f; g_bnsq1[i] = 0.f;
    }
}

__global__ void convw_kernel(const float* __restrict__ W0,
                             const float* __restrict__ W1,
                             const float* __restrict__ W2) {
    int i = blockIdx.x * blockDim.x + threadIdx.x;
    if (i < FEAT * FEAT) {
        g_Wh[0][i] = __float2half(W0[i]);
        g_Wh[1][i] = __float2half(W1[i]);
        g_Wh[2][i] = __float2half(W2[i]);
    }
}

__global__ void count_kernel(const int* __restrict__ ei) {
    int e = blockIdx.x * blockDim.x + threadIdx.x;
    if (e < NEDGES) atomicAdd(&g_cnt[ei[NEDGES + e]], 1);
}

// single-block shuffle scan -> rowptr (inclusive shifted) and off (exclusive)
__global__ void scan_kernel() {
    __shared__ int wsum[32];
    __shared__ int carry_s;
    int tid = threadIdx.x, lane = tid & 31, wid = tid >> 5;
    if (tid == 0) { carry_s = 0; g_rowptr[0] = 0; }
    __syncthreads();
    for (int base = 0; base < NNODES; base += 1024) {
        int i = base + tid;
        int v = (i < NNODES) ? g_cnt[i] : 0;
        int s = v;
#pragma unroll
        for (int o = 1; o < 32; o <<= 1) {
            int t = __shfl_up_sync(0xffffffffu, s, o);
            if (lane >= o) s += t;
        }
        if (lane == 31) wsum[wid] = s;
        __syncthreads();
        if (wid == 0) {
            int ws = wsum[lane];
#pragma unroll
            for (int o = 1; o < 32; o <<= 1) {
                int t = __shfl_up_sync(0xffffffffu, ws, o);
                if (lane >= o) ws += t;
            }
            wsum[lane] = ws;
        }
        __syncthreads();
        int incl = s + (wid ? wsum[wid - 1] : 0) + carry_s;
        if (i < NNODES) {
            g_rowptr[i + 1] = incl;
            g_off[i] = incl - v;
        }
        __syncthreads();
        if (tid == 1023) carry_s = incl;
        __syncthreads();
    }
}

__global__ void scatter_kernel(const int* __restrict__ ei) {
    int idx = blockIdx.x * blockDim.x + threadIdx.x;
    if (idx >= ETOT) return;
    int s, d;
    if (idx < NEDGES) { s = ei[idx]; d = ei[NEDGES + idx]; }
    else { s = d = idx - NEDGES; }
    int p = atomicAdd(&g_off[d], 1);
    g_csrc[p] = s;
}

// ---------------- tensor-core helpers ----------------
__device__ __forceinline__ uint32_t smem_u32(const void* p) {
    uint32_t a;
    asm("{ .reg .u64 t; cvta.to.shared.u64 t, %1; cvt.u32.u64 %0, t; }"
        : "=r"(a) : "l"(p));
    return a;
}

__device__ __forceinline__ void ldsm_x4(uint32_t& a0, uint32_t& a1, uint32_t& a2,
                                        uint32_t& a3, uint32_t addr) {
    asm volatile("ldmatrix.sync.aligned.m8n8.x4.shared.b16 {%0,%1,%2,%3}, [%4];"
                 : "=r"(a0), "=r"(a1), "=r"(a2), "=r"(a3) : "r"(addr));
}

__device__ __forceinline__ void ldsm_x2(uint32_t& b0, uint32_t& b1, uint32_t addr) {
    asm volatile("ldmatrix.sync.aligned.m8n8.x2.shared.b16 {%0,%1}, [%2];"
                 : "=r"(b0), "=r"(b1) : "r"(addr));
}

__device__ __forceinline__ void mma16816(float c[4], uint32_t a0, uint32_t a1,
                                         uint32_t a2, uint32_t a3,
                                         uint32_t b0, uint32_t b1) {
    asm volatile(
        "mma.sync.aligned.m16n8k16.row.col.f32.f16.f16.f32 "
        "{%0,%1,%2,%3}, {%4,%5,%6,%7}, {%8,%9}, {%0,%1,%2,%3};"
        : "+f"(c[0]), "+f"(c[1]), "+f"(c[2]), "+f"(c[3])
        : "r"(a0), "r"(a1), "r"(a2), "r"(a3), "r"(b0), "r"(b1));
}

// ---------------- GEMM (HMMA) + fused BN-on-load + alpha epilogue ----------------
// g_hh(fp16) = [relu(bn(X))] @ W^T ; g_as/g_ad = h . a_src / a_dst
__global__ __launch_bounds__(256) void gemm_kernel(
    const float* __restrict__ X, const __half* __restrict__ Wh,
    const float* __restrict__ asrc, const float* __restrict__ adst,
    const float* __restrict__ gamma, const float* __restrict__ beta,
    const float* __restrict__ bsum, const float* __restrict__ bsq,
    int use_bn, int M) {
    extern __shared__ __half smem[];
    __half* Xs = smem;                       // [128][LDX]
    __half* Ws = smem + 128 * LDX;           // [128][LDX]
    float* sc  = (float*)(smem + 2 * 128 * LDX);
    float* sh  = sc + FEAT;
    float* sAs = sh + FEAT;
    float* sAd = sAs + FEAT;

    int tid = threadIdx.x;
    int bm = blockIdx.x * 128;

    if (tid < FEAT) {
        sAs[tid] = asrc[tid];
        sAd[tid] = adst[tid];
        if (use_bn) {
            const float invN = 1.f / (float)NNODES;
            float mu = bsum[tid] * invN;
            float var = bsq[tid] * invN - mu * mu;
            float s = gamma[tid] * rsqrtf(var + BN_EPS);
            sc[tid] = s;
            sh[tid] = beta[tid] - mu * s;
        } else { sc[tid] = 1.f; sh[tid] = 0.f; }
    }
    __syncthreads();

    // W fp16 -> smem (2048 uint4)
    for (int idx = tid; idx < 2048; idx += 256) {
        int r = idx >> 4, c = (idx & 15) << 3;
        *(uint4*)&Ws[r * LDX + c] = *(const uint4*)&Wh[r * FEAT + c];
    }
    // X fp32 -> BN/relu -> fp16 smem (4096 float4)
    for (int idx = tid; idx < 4096; idx += 256) {
        int r = idx >> 5, c = (idx & 31) << 2;
        int gr = bm + r;
        float4 xv = make_float4(0.f, 0.f, 0.f, 0.f);
        if (gr < M) xv = *(const float4*)&X[(size_t)gr * FEAT + c];
        float y0 = xv.x * sc[c] + sh[c];
        float y1 = xv.y * sc[c + 1] + sh[c + 1];
        float y2 = xv.z * sc[c + 2] + sh[c + 2];
        float y3 = xv.w * sc[c + 3] + sh[c + 3];
        if (use_bn) {
            y0 = fmaxf(y0, 0.f); y1 = fmaxf(y1, 0.f);
            y2 = fmaxf(y2, 0.f); y3 = fmaxf(y3, 0.f);
        }
        __half2 h0 = __floats2half2_rn(y0, y1);
        __half2 h1 = __floats2half2_rn(y2, y3);
        uint2 u; u.x = *(uint32_t*)&h0; u.y = *(uint32_t*)&h1;
        *(uint2*)&Xs[r * LDX + c] = u;
    }
    __syncthreads();

    int warp = tid >> 5, lane = tid & 31;
    int m0 = warp * 16;

    float c_[16][4];
#pragma unroll
    for (int t = 0; t < 16; t++)
#pragma unroll
        for (int j = 0; j < 4; j++) c_[t][j] = 0.f;

    uint32_t sbase = smem_u32(smem);
    // A: lanes 0-15 -> rows m0+(lane&15), col 0 ; lanes 16-31 -> same rows, col 8
    uint32_t xs_addr = sbase + ((m0 + (lane & 15)) * LDX + (lane >> 4) * 8) * 2;
    // B: lanes 0-7 -> rows n0+lane, k0 ; lanes 8-15 -> rows n0+(lane-8), k0+8
    uint32_t ws_addr = sbase + (128 * LDX + (lane & 7) * LDX + ((lane >> 3) & 1) * 8) * 2;

#pragma unroll
    for (int k = 0; k < 8; k++) {
        uint32_t a0, a1, a2, a3;
        ldsm_x4(a0, a1, a2, a3, xs_addr + k * 32);   // 16 halves = 32 B per k-step
#pragma unroll
        for (int t = 0; t < 16; t++) {
            uint32_t b0, b1;
            ldsm_x2(b0, b1, ws_addr + (t * 8 * LDX) * 2 + k * 32);
            mma16816(c_[t], a0, a1, a2, a3, b0, b1);
        }
    }

    // ---- alpha epilogue: lane holds cols {8t+q, 8t+q+1} for rows r0 and r0+8
    int r0l = lane >> 2;
    int q = (lane & 3) * 2;
    float ps0 = 0.f, pd0 = 0.f, ps1 = 0.f, pd1 = 0.f;
#pragma unroll
    for (int t = 0; t < 16; t++) {
        int cA = t * 8 + q;
        float a0 = sAs[cA], a1 = sAs[cA + 1];
        float d0 = sAd[cA], d1 = sAd[cA + 1];
        ps0 += c_[t][0] * a0 + c_[t][1] * a1;
        pd0 += c_[t][0] * d0 + c_[t][1] * d1;
        ps1 += c_[t][2] * a0 + c_[t][3] * a1;
        pd1 += c_[t][2] * d0 + c_[t][3] * d1;
    }
#pragma unroll
    for (int o = 1; o < 4; o <<= 1) {
        ps0 += __shfl_xor_sync(0xffffffffu, ps0, o);
        pd0 += __shfl_xor_sync(0xffffffffu, pd0, o);
        ps1 += __shfl_xor_sync(0xffffffffu, ps1, o);
        pd1 += __shfl_xor_sync(0xffffffffu, pd1, o);
    }
    int gr0 = bm + m0 + r0l, gr1 = gr0 + 8;
    if ((lane & 3) == 0) {
        if (gr0 < M) { g_as[gr0] = ps0; g_ad[gr0] = pd0; }
        if (gr1 < M) { g_as[gr1] = ps1; g_ad[gr1] = pd1; }
    }

    // ---- stage C (fp16) into this warp's own Xs rows, then coalesced store
#pragma unroll
    for (int t = 0; t < 16; t++) {
        int colp = t * 8 + q;
        __half2 lo = __floats2half2_rn(c_[t][0], c_[t][1]);
        __half2 hi = __floats2half2_rn(c_[t][2], c_[t][3]);
        *(__half2*)&Xs[(m0 + r0l) * LDX + colp] = lo;
        *(__half2*)&Xs[(m0 + r0l + 8) * LDX + colp] = hi;
    }
    __syncwarp();
    for (int i = lane; i < 256; i += 32) {
        int r = i >> 4, ch = (i & 15) << 3;
        int gr = bm + m0 + r;
        if (gr < M)
            *(uint4*)&g_hh[(size_t)gr * FEAT + ch] = *(uint4*)&Xs[(m0 + r) * LDX + ch];
    }
}

__device__ __forceinline__ float leaky(float x) {
    return x >= 0.f ? x : NEG_SLOPE * x;
}

// ---------------- edge softmax + aggregation (warp per dst) + BN-stat epilogue ----------------
__global__ __launch_bounds__(256) void edge_kernel(const float* __restrict__ bias,
                                                   float* __restrict__ out,
                                                   float* __restrict__ bnsum,
                                                   float* __restrict__ bnsq,
                                                   int do_bn) {
    __shared__ float  ew[8][64];
    __shared__ float4 psum[8][32];
    __shared__ float4 psq[8][32];
    int tid = threadIdx.x, w = tid >> 5, lane = tid & 31;
    int d = blockIdx.x * 8 + w;            // grid = 12500 exactly
    int beg = g_rowptr[d], end = g_rowptr[d + 1];
    int deg = end - beg;
    float ad = g_ad[d];
    float m, inv;
    bool cached = (deg <= 64);

    if (cached) {
        float e0 = -1e30f, e1 = -1e30f;
        if (lane < deg)      e0 = leaky(g_as[g_csrc[beg + lane]] + ad);
        if (32 + lane < deg) e1 = leaky(g_as[g_csrc[beg + 32 + lane]] + ad);
        m = fmaxf(e0, e1);
#pragma unroll
        for (int o = 16; o; o >>= 1) m = fmaxf(m, __shfl_xor_sync(0xffffffffu, m, o));
        float x0 = (lane < deg)      ? __expf(e0 - m) : 0.f;
        float x1 = (32 + lane < deg) ? __expf(e1 - m) : 0.f;
        ew[w][lane] = x0; ew[w][lane + 32] = x1;
        float sum = x0 + x1;
#pragma unroll
        for (int o = 16; o; o >>= 1) sum += __shfl_xor_sync(0xffffffffu, sum, o);
        inv = 1.f / sum;
        __syncwarp();
    } else {
        m = -1e30f;
        for (int i = beg + lane; i < end; i += 32)
            m = fmaxf(m, leaky(g_as[g_csrc[i]] + ad));
#pragma unroll
        for (int o = 16; o; o >>= 1) m = fmaxf(m, __shfl_xor_sync(0xffffffffu, m, o));
        float sum = 0.f;
        for (int i = beg + lane; i < end; i += 32)
            sum += __expf(leaky(g_as[g_csrc[i]] + ad) - m);
#pragma unroll
        for (int o = 16; o; o >>= 1) sum += __shfl_xor_sync(0xffffffffu, sum, o);
        inv = 1.f / sum;
    }

    float ax = 0.f, ay = 0.f, az = 0.f, aw = 0.f;
    const uint2* h2 = (const uint2*)g_hh;
#pragma unroll 2
    for (int i = 0; i < deg; i++) {
        int s = g_csrc[beg + i];
        float wt = cached ? ew[w][i] * inv
                          : __expf(leaky(g_as[s] + ad) - m) * inv;
        uint2 raw = h2[(size_t)s * 32 + lane];   // 8B/lane = 256B/edge
        float2 f0 = __half22float2(*(__half2*)&raw.x);
        float2 f1 = __half22float2(*(__half2*)&raw.y);
        ax += wt * f0.x; ay += wt * f0.y; az += wt * f1.x; aw += wt * f1.y;
    }
    float4 bb = ((const float4*)bias)[lane];
    float4 o = make_float4(ax + bb.x, ay + bb.y, az + bb.z, aw + bb.w);
    ((float4*)out)[(size_t)d * 32 + lane] = o;

    if (do_bn) {
        psum[w][lane] = o;
        psq[w][lane]  = make_float4(o.x * o.x, o.y * o.y, o.z * o.z, o.w * o.w);
        __syncthreads();
        if (tid < FEAT) {
            float s = 0.f, q = 0.f;
            const float* ps = (const float*)psum;
            const float* pq = (const float*)psq;
#pragma unroll
            for (int ww = 0; ww < 8; ww++) {
                s += ps[ww * 128 + tid];
                q += pq[ww * 128 + tid];
            }
            atomicAdd(&bnsum[tid], s);
            atomicAdd(&bnsq[tid], q);
        }
    }
}

// ---------------- launch ----------------
extern "C" void kernel_launch(void* const* d_in, const int* in_sizes, int n_in,
                              void* d_out, int out_size) {
    const float* x  = (const float*)d_in[0];
    const int*   ei = (const int*)d_in[1];
    const float* W[3]  = {(const float*)d_in[2], (const float*)d_in[6],  (const float*)d_in[10]};
    const float* As[3] = {(const float*)d_in[3], (const float*)d_in[7],  (const float*)d_in[11]};
    const float* Ad[3] = {(const float*)d_in[4], (const float*)d_in[8],  (const float*)d_in[12]};
    const float* B[3]  = {(const float*)d_in[5], (const float*)d_in[9],  (const float*)d_in[13]};
    const float* gam[2] = {(const float*)d_in[14], (const float*)d_in[16]};
    const float* bet[2] = {(const float*)d_in[15], (const float*)d_in[17]};

    float *acc_ptr, *bs0, *bq0, *bs1, *bq1;
    __half* wh_ptr;
    cudaGetSymbolAddress((void**)&acc_ptr, g_acc);
    cudaGetSymbolAddress((void**)&bs0, g_bnsum0);
    cudaGetSymbolAddress((void**)&bq0, g_bnsq0);
    cudaGetSymbolAddress((void**)&bs1, g_bnsum1);
    cudaGetSymbolAddress((void**)&bq1, g_bnsq1);
    cudaGetSymbolAddress((void**)&wh_ptr, g_Wh);

    const int SMEM_GEMM = (2 * 128 * LDX) * 2 + 4 * FEAT * 4;   // 71680 B
    cudaFuncSetAttribute(gemm_kernel,
                         cudaFuncAttributeMaxDynamicSharedMemorySize, SMEM_GEMM);

    // CSR build + weight convert
    init_kernel<<<(NNODES + 255) / 256, 256>>>();
    convw_kernel<<<(FEAT * FEAT + 255) / 256, 256>>>(W[0], W[1], W[2]);
    count_kernel<<<(NEDGES + 255) / 256, 256>>>(ei);
    scan_kernel<<<1, 1024>>>();
    scatter_kernel<<<(ETOT + 255) / 256, 256>>>(ei);

    const int gemm_grid = (NNODES + 127) / 128;   // 782
    const int edge_grid = NNODES / 8;             // 12500

    // layer 0
    gemm_kernel<<<gemm_grid, 256, SMEM_GEMM>>>(x, wh_ptr, As[0], Ad[0],
                                               nullptr, nullptr, nullptr, nullptr, 0, NNODES);
    edge_kernel<<<edge_grid, 256>>>(B[0], acc_ptr, bs0, bq0, 1);
    // layer 1 (BN0+relu fused into X load)
    gemm_kernel<<<gemm_grid, 256, SMEM_GEMM>>>(acc_ptr, wh_ptr + FEAT * FEAT, As[1], Ad[1],
                                               gam[0], bet[0], bs0, bq0, 1, NNODES);
    edge_kernel<<<edge_grid, 256>>>(B[1], acc_ptr, bs1, bq1, 1);
    // layer 2 (BN1+relu fused into X load)
    gemm_kernel<<<gemm_grid, 256, SMEM_GEMM>>>(acc_ptr, wh_ptr + 2 * FEAT * FEAT, As[2], Ad[2],
                                               gam[1], bet[1], bs1, bq1, 1, NNODES);
    edge_kernel<<<edge_grid, 256>>>(B[2], (float*)d_out, nullptr, nullptr, 0);
}

// round 5
// speedup vs baseline: 2.0306x; 1.1156x over previous
#include <cuda_runtime.h>
#include <cuda_fp16.h>
#include <cstdint>

#define NNODES 100000
#define FEAT   128
#define NEDGES 1600000
#define ETOT   (NEDGES + NNODES)
#define BN_EPS 1e-5f
#define NEG_SLOPE 0.2f
#define LDX    136   // padded smem row pitch in halves (272B: conflict-free ldmatrix)
#define SCAN_BLOCKS ((NNODES + 1023) / 1024)   // 98

// ---------------- static device scratch ----------------
__device__ __half g_hh[(size_t)NNODES * FEAT];   // h in fp16 (gather payload)
__device__ float  g_acc[(size_t)NNODES * FEAT];  // layer output / next input (fp32)
__device__ __half g_Wh[3][FEAT * FEAT];          // fp16 weights
__device__ float  g_as[NNODES];
__device__ float  g_ad[NNODES];
__device__ int    g_cnt[NNODES];
__device__ int    g_rowptr[NNODES + 1];
__device__ int    g_off[NNODES];
__device__ int    g_csrc[ETOT];
__device__ int    g_bsum[SCAN_BLOCKS];
__device__ int    g_bpre[SCAN_BLOCKS];
__device__ float  g_bnsum0[FEAT], g_bnsq0[FEAT];
__device__ float  g_bnsum1[FEAT], g_bnsq1[FEAT];

// ---------------- weight convert ----------------
__global__ void convw_kernel(const float* __restrict__ W0,
                             const float* __restrict__ W1,
                             const float* __restrict__ W2) {
    int i = blockIdx.x * blockDim.x + threadIdx.x;
    if (i < FEAT * FEAT) {
        g_Wh[0][i] = __float2half(W0[i]);
        g_Wh[1][i] = __float2half(W1[i]);
        g_Wh[2][i] = __float2half(W2[i]);
    }
}

__global__ void count_kernel(const int* __restrict__ ei) {
    int e = blockIdx.x * blockDim.x + threadIdx.x;
    if (e < NEDGES) atomicAdd(&g_cnt[ei[NEDGES + e]], 1);
}

// ---------------- multi-block scan ----------------
// phase 1: per-block inclusive scan of (cnt[i]+1); block totals to g_bsum
__global__ __launch_bounds__(1024) void scan1_kernel() {
    __shared__ int wsum[32];
    int tid = threadIdx.x, lane = tid & 31, wid = tid >> 5;
    int i = blockIdx.x * 1024 + tid;
    int v = (i < NNODES) ? g_cnt[i] + 1 : 0;   // +1 = self loop
    int s = v;
#pragma unroll
    for (int o = 1; o < 32; o <<= 1) {
        int t = __shfl_up_sync(0xffffffffu, s, o);
        if (lane >= o) s += t;
    }
    if (lane == 31) wsum[wid] = s;
    __syncthreads();
    if (wid == 0) {
        int ws = wsum[lane];
#pragma unroll
        for (int o = 1; o < 32; o <<= 1) {
            int t = __shfl_up_sync(0xffffffffu, ws, o);
            if (lane >= o) ws += t;
        }
        wsum[lane] = ws;
    }
    __syncthreads();
    int incl = s + (wid ? wsum[wid - 1] : 0);
    if (i < NNODES) g_rowptr[i + 1] = incl;    // local inclusive, fixed in phase 3
    if (tid == 1023) g_bsum[blockIdx.x] = incl;
}

// phase 2: one block scans 98 block sums -> exclusive prefixes
__global__ __launch_bounds__(128) void scan2_kernel() {
    __shared__ int wsum[4];
    int tid = threadIdx.x, lane = tid & 31, wid = tid >> 5;
    int v = (tid < SCAN_BLOCKS) ? g_bsum[tid] : 0;
    int s = v;
#pragma unroll
    for (int o = 1; o < 32; o <<= 1) {
        int t = __shfl_up_sync(0xffffffffu, s, o);
        if (lane >= o) s += t;
    }
    if (lane == 31) wsum[wid] = s;
    __syncthreads();
    int carry = 0;
    for (int w = 0; w < wid; w++) carry += wsum[w];
    if (tid < SCAN_BLOCKS) g_bpre[tid] = s - v + carry;   // exclusive
}

// phase 3: add block prefix; emit rowptr & off
__global__ __launch_bounds__(1024) void scan3_kernel() {
    int tid = threadIdx.x;
    int i = blockIdx.x * 1024 + tid;
    if (i == 0) g_rowptr[0] = 0;
    if (i < NNODES) {
        int incl = g_rowptr[i + 1] + g_bpre[blockIdx.x];
        g_rowptr[i + 1] = incl;
        g_off[i] = incl - (g_cnt[i] + 1);
    }
}

__global__ void scatter_kernel(const int* __restrict__ ei) {
    int idx = blockIdx.x * blockDim.x + threadIdx.x;
    if (idx >= ETOT) return;
    int s, d;
    if (idx < NEDGES) { s = ei[idx]; d = ei[NEDGES + idx]; }
    else { s = d = idx - NEDGES; }
    int p = atomicAdd(&g_off[d], 1);
    g_csrc[p] = s;
}

// ---------------- tensor-core helpers ----------------
__device__ __forceinline__ uint32_t smem_u32(const void* p) {
    uint32_t a;
    asm("{ .reg .u64 t; cvta.to.shared.u64 t, %1; cvt.u32.u64 %0, t; }"
        : "=r"(a) : "l"(p));
    return a;
}

__device__ __forceinline__ void ldsm_x4(uint32_t& a0, uint32_t& a1, uint32_t& a2,
                                        uint32_t& a3, uint32_t addr) {
    asm volatile("ldmatrix.sync.aligned.m8n8.x4.shared.b16 {%0,%1,%2,%3}, [%4];"
                 : "=r"(a0), "=r"(a1), "=r"(a2), "=r"(a3) : "r"(addr));
}

__device__ __forceinline__ void ldsm_x2(uint32_t& b0, uint32_t& b1, uint32_t addr) {
    asm volatile("ldmatrix.sync.aligned.m8n8.x2.shared.b16 {%0,%1}, [%2];"
                 : "=r"(b0), "=r"(b1) : "r"(addr));
}

__device__ __forceinline__ void mma16816(float c[4], uint32_t a0, uint32_t a1,
                                         uint32_t a2, uint32_t a3,
                                         uint32_t b0, uint32_t b1) {
    asm volatile(
        "mma.sync.aligned.m16n8k16.row.col.f32.f16.f16.f32 "
        "{%0,%1,%2,%3}, {%4,%5,%6,%7}, {%8,%9}, {%0,%1,%2,%3};"
        : "+f"(c[0]), "+f"(c[1]), "+f"(c[2]), "+f"(c[3])
        : "r"(a0), "r"(a1), "r"(a2), "r"(a3), "r"(b0), "r"(b1));
}

// ---------------- GEMM (HMMA) + fused BN-on-load + alpha epilogue ----------------
__global__ __launch_bounds__(256) void gemm_kernel(
    const float* __restrict__ X, const __half* __restrict__ Wh,
    const float* __restrict__ asrc, const float* __restrict__ adst,
    const float* __restrict__ gamma, const float* __restrict__ beta,
    const float* __restrict__ bsum, const float* __restrict__ bsq,
    int use_bn, int M) {
    extern __shared__ __half smem[];
    __half* Xs = smem;                       // [128][LDX]
    __half* Ws = smem + 128 * LDX;           // [128][LDX]
    float* sc  = (float*)(smem + 2 * 128 * LDX);
    float* sh  = sc + FEAT;
    float* sAs = sh + FEAT;
    float* sAd = sAs + FEAT;

    int tid = threadIdx.x;
    int bm = blockIdx.x * 128;

    if (tid < FEAT) {
        sAs[tid] = asrc[tid];
        sAd[tid] = adst[tid];
        if (use_bn) {
            const float invN = 1.f / (float)NNODES;
            float mu = bsum[tid] * invN;
            float var = bsq[tid] * invN - mu * mu;
            float s = gamma[tid] * rsqrtf(var + BN_EPS);
            sc[tid] = s;
            sh[tid] = beta[tid] - mu * s;
        } else { sc[tid] = 1.f; sh[tid] = 0.f; }
    }
    __syncthreads();

    // W fp16 -> smem (2048 uint4)
    for (int idx = tid; idx < 2048; idx += 256) {
        int r = idx >> 4, c = (idx & 15) << 3;
        *(uint4*)&Ws[r * LDX + c] = *(const uint4*)&Wh[r * FEAT + c];
    }
    // X fp32 -> BN/relu -> fp16 smem (4096 float4)
    for (int idx = tid; idx < 4096; idx += 256) {
        int r = idx >> 5, c = (idx & 31) << 2;
        int gr = bm + r;
        float4 xv = make_float4(0.f, 0.f, 0.f, 0.f);
        if (gr < M) xv = *(const float4*)&X[(size_t)gr * FEAT + c];
        float y0 = xv.x * sc[c] + sh[c];
        float y1 = xv.y * sc[c + 1] + sh[c + 1];
        float y2 = xv.z * sc[c + 2] + sh[c + 2];
        float y3 = xv.w * sc[c + 3] + sh[c + 3];
        if (use_bn) {
            y0 = fmaxf(y0, 0.f); y1 = fmaxf(y1, 0.f);
            y2 = fmaxf(y2, 0.f); y3 = fmaxf(y3, 0.f);
        }
        __half2 h0 = __floats2half2_rn(y0, y1);
        __half2 h1 = __floats2half2_rn(y2, y3);
        uint2 u; u.x = *(uint32_t*)&h0; u.y = *(uint32_t*)&h1;
        *(uint2*)&Xs[r * LDX + c] = u;
    }
    __syncthreads();

    int warp = tid >> 5, lane = tid & 31;
    int m0 = warp * 16;

    float c_[16][4];
#pragma unroll
    for (int t = 0; t < 16; t++)
#pragma unroll
        for (int j = 0; j < 4; j++) c_[t][j] = 0.f;

    uint32_t sbase = smem_u32(smem);
    uint32_t xs_addr = sbase + ((m0 + (lane & 15)) * LDX + (lane >> 4) * 8) * 2;
    uint32_t ws_addr = sbase + (128 * LDX + (lane & 7) * LDX + ((lane >> 3) & 1) * 8) * 2;

#pragma unroll
    for (int k = 0; k < 8; k++) {
        uint32_t a0, a1, a2, a3;
        ldsm_x4(a0, a1, a2, a3, xs_addr + k * 32);   // 16 halves = 32 B per k-step
#pragma unroll
        for (int t = 0; t < 16; t++) {
            uint32_t b0, b1;
            ldsm_x2(b0, b1, ws_addr + (t * 8 * LDX) * 2 + k * 32);
            mma16816(c_[t], a0, a1, a2, a3, b0, b1);
        }
    }

    // ---- alpha epilogue
    int r0l = lane >> 2;
    int q = (lane & 3) * 2;
    float ps0 = 0.f, pd0 = 0.f, ps1 = 0.f, pd1 = 0.f;
#pragma unroll
    for (int t = 0; t < 16; t++) {
        int cA = t * 8 + q;
        float a0 = sAs[cA], a1 = sAs[cA + 1];
        float d0 = sAd[cA], d1 = sAd[cA + 1];
        ps0 += c_[t][0] * a0 + c_[t][1] * a1;
        pd0 += c_[t][0] * d0 + c_[t][1] * d1;
        ps1 += c_[t][2] * a0 + c_[t][3] * a1;
        pd1 += c_[t][2] * d0 + c_[t][3] * d1;
    }
#pragma unroll
    for (int o = 1; o < 4; o <<= 1) {
        ps0 += __shfl_xor_sync(0xffffffffu, ps0, o);
        pd0 += __shfl_xor_sync(0xffffffffu, pd0, o);
        ps1 += __shfl_xor_sync(0xffffffffu, ps1, o);
        pd1 += __shfl_xor_sync(0xffffffffu, pd1, o);
    }
    int gr0 = bm + m0 + r0l, gr1 = gr0 + 8;
    if ((lane & 3) == 0) {
        if (gr0 < M) { g_as[gr0] = ps0; g_ad[gr0] = pd0; }
        if (gr1 < M) { g_as[gr1] = ps1; g_ad[gr1] = pd1; }
    }

    // ---- stage C (fp16) into this warp's own Xs rows, then coalesced store
#pragma unroll
    for (int t = 0; t < 16; t++) {
        int colp = t * 8 + q;
        __half2 lo = __floats2half2_rn(c_[t][0], c_[t][1]);
        __half2 hi = __floats2half2_rn(c_[t][2], c_[t][3]);
        *(__half2*)&Xs[(m0 + r0l) * LDX + colp] = lo;
        *(__half2*)&Xs[(m0 + r0l + 8) * LDX + colp] = hi;
    }
    __syncwarp();
    for (int i = lane; i < 256; i += 32) {
        int r = i >> 4, ch = (i & 15) << 3;
        int gr = bm + m0 + r;
        if (gr < M)
            *(uint4*)&g_hh[(size_t)gr * FEAT + ch] = *(uint4*)&Xs[(m0 + r) * LDX + ch];
    }
}

__device__ __forceinline__ float leaky(float x) {
    return x >= 0.f ? x : NEG_SLOPE * x;
}

// ---------------- edge softmax + aggregation (warp per dst) + BN-stat epilogue ----------------
__global__ __launch_bounds__(256) void edge_kernel(const float* __restrict__ bias,
                                                   float* __restrict__ out,
                                                   float* __restrict__ bnsum,
                                                   float* __restrict__ bnsq,
                                                   int do_bn) {
    __shared__ float  ew[8][64];
    __shared__ float4 psum[8][32];
    __shared__ float4 psq[8][32];
    int tid = threadIdx.x, w = tid >> 5, lane = tid & 31;
    int d = blockIdx.x * 8 + w;            // grid = 12500 exactly
    int beg = g_rowptr[d], end = g_rowptr[d + 1];
    int deg = end - beg;
    float ad = g_ad[d];
    float m, inv;
    bool cached = (deg <= 64);

    if (cached) {
        float e0 = -1e30f, e1 = -1e30f;
        if (lane < deg)      e0 = leaky(g_as[g_csrc[beg + lane]] + ad);
        if (32 + lane < deg) e1 = leaky(g_as[g_csrc[beg + 32 + lane]] + ad);
        m = fmaxf(e0, e1);
#pragma unroll
        for (int o = 16; o; o >>= 1) m = fmaxf(m, __shfl_xor_sync(0xffffffffu, m, o));
        float x0 = (lane < deg)      ? __expf(e0 - m) : 0.f;
        float x1 = (32 + lane < deg) ? __expf(e1 - m) : 0.f;
        ew[w][lane] = x0; ew[w][lane + 32] = x1;
        float sum = x0 + x1;
#pragma unroll
        for (int o = 16; o; o >>= 1) sum += __shfl_xor_sync(0xffffffffu, sum, o);
        inv = 1.f / sum;
        __syncwarp();
    } else {
        m = -1e30f;
        for (int i = beg + lane; i < end; i += 32)
            m = fmaxf(m, leaky(g_as[g_csrc[i]] + ad));
#pragma unroll
        for (int o = 16; o; o >>= 1) m = fmaxf(m, __shfl_xor_sync(0xffffffffu, m, o));
        float sum = 0.f;
        for (int i = beg + lane; i < end; i += 32)
            sum += __expf(leaky(g_as[g_csrc[i]] + ad) - m);
#pragma unroll
        for (int o = 16; o; o >>= 1) sum += __shfl_xor_sync(0xffffffffu, sum, o);
        inv = 1.f / sum;
    }

    float ax = 0.f, ay = 0.f, az = 0.f, aw = 0.f;
    const uint2* h2 = (const uint2*)g_hh;
#pragma unroll 2
    for (int i = 0; i < deg; i++) {
        int s = g_csrc[beg + i];
        float wt = cached ? ew[w][i] * inv
                          : __expf(leaky(g_as[s] + ad) - m) * inv;
        uint2 raw = h2[(size_t)s * 32 + lane];   // 8B/lane = 256B/edge
        float2 f0 = __half22float2(*(__half2*)&raw.x);
        float2 f1 = __half22float2(*(__half2*)&raw.y);
        ax += wt * f0.x; ay += wt * f0.y; az += wt * f1.x; aw += wt * f1.y;
    }
    float4 bb = ((const float4*)bias)[lane];
    float4 o = make_float4(ax + bb.x, ay + bb.y, az + bb.z, aw + bb.w);
    ((float4*)out)[(size_t)d * 32 + lane] = o;

    if (do_bn) {
        psum[w][lane] = o;
        psq[w][lane]  = make_float4(o.x * o.x, o.y * o.y, o.z * o.z, o.w * o.w);
        __syncthreads();
        if (tid < FEAT) {
            float s = 0.f, q = 0.f;
            const float* ps = (const float*)psum;
            const float* pq = (const float*)psq;
#pragma unroll
            for (int ww = 0; ww < 8; ww++) {
                s += ps[ww * 128 + tid];
                q += pq[ww * 128 + tid];
            }
            atomicAdd(&bnsum[tid], s);
            atomicAdd(&bnsq[tid], q);
        }
    }
}

// ---------------- launch ----------------
extern "C" void kernel_launch(void* const* d_in, const int* in_sizes, int n_in,
                              void* d_out, int out_size) {
    const float* x  = (const float*)d_in[0];
    const int*   ei = (const int*)d_in[1];
    const float* W[3]  = {(const float*)d_in[2], (const float*)d_in[6],  (const float*)d_in[10]};
    const float* As[3] = {(const float*)d_in[3], (const float*)d_in[7],  (const float*)d_in[11]};
    const float* Ad[3] = {(const float*)d_in[4], (const float*)d_in[8],  (const float*)d_in[12]};
    const float* B[3]  = {(const float*)d_in[5], (const float*)d_in[9],  (const float*)d_in[13]};
    const float* gam[2] = {(const float*)d_in[14], (const float*)d_in[16]};
    const float* bet[2] = {(const float*)d_in[15], (const float*)d_in[17]};

    float *acc_ptr, *bs0, *bq0, *bs1, *bq1;
    int* cnt_ptr;
    __half* wh_ptr;
    cudaGetSymbolAddress((void**)&acc_ptr, g_acc);
    cudaGetSymbolAddress((void**)&bs0, g_bnsum0);
    cudaGetSymbolAddress((void**)&bq0, g_bnsq0);
    cudaGetSymbolAddress((void**)&bs1, g_bnsum1);
    cudaGetSymbolAddress((void**)&bq1, g_bnsq1);
    cudaGetSymbolAddress((void**)&cnt_ptr, g_cnt);
    cudaGetSymbolAddress((void**)&wh_ptr, g_Wh);

    const int SMEM_GEMM = (2 * 128 * LDX) * 2 + 4 * FEAT * 4;   // 71680 B
    cudaFuncSetAttribute(gemm_kernel,
                         cudaFuncAttributeMaxDynamicSharedMemorySize, SMEM_GEMM);

    // zero counters + BN accumulators (capturable async memsets)
    cudaMemsetAsync(cnt_ptr, 0, NNODES * sizeof(int));
    cudaMemsetAsync(bs0, 0, FEAT * sizeof(float));
    cudaMemsetAsync(bq0, 0, FEAT * sizeof(float));
    cudaMemsetAsync(bs1, 0, FEAT * sizeof(float));
    cudaMemsetAsync(bq1, 0, FEAT * sizeof(float));

    // CSR build + weight convert
    convw_kernel<<<(FEAT * FEAT + 255) / 256, 256>>>(W[0], W[1], W[2]);
    count_kernel<<<(NEDGES + 255) / 256, 256>>>(ei);
    scan1_kernel<<<SCAN_BLOCKS, 1024>>>();
    scan2_kernel<<<1, 128>>>();
    scan3_kernel<<<SCAN_BLOCKS, 1024>>>();
    scatter_kernel<<<(ETOT + 255) / 256, 256>>>(ei);

    const int gemm_grid = (NNODES + 127) / 128;   // 782
    const int edge_grid = NNODES / 8;             // 12500

    // layer 0
    gemm_kernel<<<gemm_grid, 256, SMEM_GEMM>>>(x, wh_ptr, As[0], Ad[0],
                                               nullptr, nullptr, nullptr, nullptr, 0, NNODES);
    edge_kernel<<<edge_grid, 256>>>(B[0], acc_ptr, bs0, bq0, 1);
    // layer 1 (BN0+relu fused into X load)
    gemm_kernel<<<gemm_grid, 256, SMEM_GEMM>>>(acc_ptr, wh_ptr + FEAT * FEAT, As[1], Ad[1],
                                               gam[0], bet[0], bs0, bq0, 1, NNODES);
    edge_kernel<<<edge_grid, 256>>>(B[1], acc_ptr, bs1, bq1, 1);
    // layer 2 (BN1+relu fused into X load)
    gemm_kernel<<<gemm_grid, 256, SMEM_GEMM>>>(acc_ptr, wh_ptr + 2 * FEAT * FEAT, As[2], Ad[2],
                                               gam[1], bet[1], bs1, bq1, 1, NNODES);
    edge_kernel<<<edge_grid, 256>>>(B[2], (float*)d_out, nullptr, nullptr, 0);
}

// round 6
// speedup vs baseline: 2.3007x; 1.1331x over previous
#include <cuda_runtime.h>
#include <cuda_fp16.h>
#include <cstdint>

#define NNODES 100000
#define FEAT   128
#define NEDGES 1600000
#define ETOT   (NEDGES + NNODES)
#define BN_EPS 1e-5f
#define NEG_SLOPE 0.2f
#define LDX    136   // padded smem row pitch in halves (272B: conflict-free ldmatrix)
#define SCAN_BLOCKS ((NNODES + 1023) / 1024)   // 98

// ---------------- static device scratch ----------------
__device__ __half g_hh[(size_t)NNODES * FEAT];    // h of current layer (fp16)
__device__ __half g_acch[(size_t)NNODES * FEAT];  // inter-layer activation (fp16)
__device__ __half g_Wh[3][FEAT * FEAT];           // fp16 weights
__device__ float  g_as[NNODES];
__device__ float  g_ad[NNODES];
__device__ int    g_cnt[NNODES];
__device__ int    g_rowptr[NNODES + 1];
__device__ int    g_off[NNODES];
__device__ int    g_csrc[ETOT];
__device__ int    g_bsum[SCAN_BLOCKS];
__device__ int    g_bpre[SCAN_BLOCKS];
__device__ float  g_bnsum0[FEAT], g_bnsq0[FEAT];
__device__ float  g_bnsum1[FEAT], g_bnsq1[FEAT];

// ---------------- weight convert + BN accumulator zero ----------------
__global__ void convw_kernel(const float* __restrict__ W0,
                             const float* __restrict__ W1,
                             const float* __restrict__ W2) {
    int i = blockIdx.x * blockDim.x + threadIdx.x;
    if (i < FEAT) {
        g_bnsum0[i] = 0.f; g_bnsq0[i] = 0.f;
        g_bnsum1[i] = 0.f; g_bnsq1[i] = 0.f;
    }
    if (i < FEAT * FEAT) {
        g_Wh[0][i] = __float2half(W0[i]);
        g_Wh[1][i] = __float2half(W1[i]);
        g_Wh[2][i] = __float2half(W2[i]);
    }
}

__global__ void count_kernel(const int* __restrict__ ei) {
    int e = blockIdx.x * blockDim.x + threadIdx.x;
    if (e < NEDGES) atomicAdd(&g_cnt[ei[NEDGES + e]], 1);
}

// ---------------- multi-block scan ----------------
__global__ __launch_bounds__(1024) void scan1_kernel() {
    __shared__ int wsum[32];
    int tid = threadIdx.x, lane = tid & 31, wid = tid >> 5;
    int i = blockIdx.x * 1024 + tid;
    int v = (i < NNODES) ? g_cnt[i] + 1 : 0;   // +1 = self loop
    int s = v;
#pragma unroll
    for (int o = 1; o < 32; o <<= 1) {
        int t = __shfl_up_sync(0xffffffffu, s, o);
        if (lane >= o) s += t;
    }
    if (lane == 31) wsum[wid] = s;
    __syncthreads();
    if (wid == 0) {
        int ws = wsum[lane];
#pragma unroll
        for (int o = 1; o < 32; o <<= 1) {
            int t = __shfl_up_sync(0xffffffffu, ws, o);
            if (lane >= o) ws += t;
        }
        wsum[lane] = ws;
    }
    __syncthreads();
    int incl = s + (wid ? wsum[wid - 1] : 0);
    if (i < NNODES) g_rowptr[i + 1] = incl;
    if (tid == 1023) g_bsum[blockIdx.x] = incl;
}

__global__ __launch_bounds__(128) void scan2_kernel() {
    __shared__ int wsum[4];
    int tid = threadIdx.x, lane = tid & 31, wid = tid >> 5;
    int v = (tid < SCAN_BLOCKS) ? g_bsum[tid] : 0;
    int s = v;
#pragma unroll
    for (int o = 1; o < 32; o <<= 1) {
        int t = __shfl_up_sync(0xffffffffu, s, o);
        if (lane >= o) s += t;
    }
    if (lane == 31) wsum[wid] = s;
    __syncthreads();
    int carry = 0;
    for (int w = 0; w < wid; w++) carry += wsum[w];
    if (tid < SCAN_BLOCKS) g_bpre[tid] = s - v + carry;
}

__global__ __launch_bounds__(1024) void scan3_kernel() {
    int tid = threadIdx.x;
    int i = blockIdx.x * 1024 + tid;
    if (i == 0) g_rowptr[0] = 0;
    if (i < NNODES) {
        int incl = g_rowptr[i + 1] + g_bpre[blockIdx.x];
        g_rowptr[i + 1] = incl;
        g_off[i] = incl - (g_cnt[i] + 1);
    }
}

__global__ void scatter_kernel(const int* __restrict__ ei) {
    int idx = blockIdx.x * blockDim.x + threadIdx.x;
    if (idx >= ETOT) return;
    int s, d;
    if (idx < NEDGES) { s = ei[idx]; d = ei[NEDGES + idx]; }
    else { s = d = idx - NEDGES; }
    int p = atomicAdd(&g_off[d], 1);
    g_csrc[p] = s;
}

// ---------------- tensor-core helpers ----------------
__device__ __forceinline__ uint32_t smem_u32(const void* p) {
    uint32_t a;
    asm("{ .reg .u64 t; cvta.to.shared.u64 t, %1; cvt.u32.u64 %0, t; }"
        : "=r"(a) : "l"(p));
    return a;
}

__device__ __forceinline__ void ldsm_x4(uint32_t& a0, uint32_t& a1, uint32_t& a2,
                                        uint32_t& a3, uint32_t addr) {
    asm volatile("ldmatrix.sync.aligned.m8n8.x4.shared.b16 {%0,%1,%2,%3}, [%4];"
                 : "=r"(a0), "=r"(a1), "=r"(a2), "=r"(a3) : "r"(addr));
}

__device__ __forceinline__ void ldsm_x2(uint32_t& b0, uint32_t& b1, uint32_t addr) {
    asm volatile("ldmatrix.sync.aligned.m8n8.x2.shared.b16 {%0,%1}, [%2];"
                 : "=r"(b0), "=r"(b1) : "r"(addr));
}

__device__ __forceinline__ void mma16816(float c[4], uint32_t a0, uint32_t a1,
                                         uint32_t a2, uint32_t a3,
                                         uint32_t b0, uint32_t b1) {
    asm volatile(
        "mma.sync.aligned.m16n8k16.row.col.f32.f16.f16.f32 "
        "{%0,%1,%2,%3}, {%4,%5,%6,%7}, {%8,%9}, {%0,%1,%2,%3};"
        : "+f"(c[0]), "+f"(c[1]), "+f"(c[2]), "+f"(c[3])
        : "r"(a0), "r"(a1), "r"(a2), "r"(a3), "r"(b0), "r"(b1));
}

// ---------------- GEMM (HMMA) + fused BN-on-load + alpha epilogue ----------------
// X is fp32 (layer 0) or fp16 (layers 1-2, from g_acch).
__global__ __launch_bounds__(256) void gemm_kernel(
    const float* __restrict__ Xf, const __half* __restrict__ Xh,
    const __half* __restrict__ Wh,
    const float* __restrict__ asrc, const float* __restrict__ adst,
    const float* __restrict__ gamma, const float* __restrict__ beta,
    const float* __restrict__ bsum, const float* __restrict__ bsq,
    int use_bn, int M) {
    extern __shared__ __half smem[];
    __half* Xs = smem;                       // [128][LDX]
    __half* Ws = smem + 128 * LDX;           // [128][LDX]
    float* sc  = (float*)(smem + 2 * 128 * LDX);
    float* sh  = sc + FEAT;
    float* sAs = sh + FEAT;
    float* sAd = sAs + FEAT;

    int tid = threadIdx.x;
    int bm = blockIdx.x * 128;

    if (tid < FEAT) {
        sAs[tid] = asrc[tid];
        sAd[tid] = adst[tid];
        if (use_bn) {
            const float invN = 1.f / (float)NNODES;
            float mu = bsum[tid] * invN;
            float var = bsq[tid] * invN - mu * mu;
            float s = gamma[tid] * rsqrtf(var + BN_EPS);
            sc[tid] = s;
            sh[tid] = beta[tid] - mu * s;
        } else { sc[tid] = 1.f; sh[tid] = 0.f; }
    }
    __syncthreads();

    // W fp16 -> smem (2048 uint4)
    for (int idx = tid; idx < 2048; idx += 256) {
        int r = idx >> 4, c = (idx & 15) << 3;
        *(uint4*)&Ws[r * LDX + c] = *(const uint4*)&Wh[r * FEAT + c];
    }
    if (Xh) {
        // fp16 X: 2048 uint4 of 8 halves, BN+relu applied in fp32
        for (int idx = tid; idx < 2048; idx += 256) {
            int r = idx >> 4, c = (idx & 15) << 3;
            int gr = bm + r;
            uint4 u = make_uint4(0u, 0u, 0u, 0u);
            if (gr < M) u = *(const uint4*)&Xh[(size_t)gr * FEAT + c];
            __half2* hp = (__half2*)&u;
            uint4 outv;
            __half2* op = (__half2*)&outv;
#pragma unroll
            for (int j = 0; j < 4; j++) {
                float2 f = __half22float2(hp[j]);
                int cc = c + j * 2;
                float y0 = f.x * sc[cc] + sh[cc];
                float y1 = f.y * sc[cc + 1] + sh[cc + 1];
                y0 = fmaxf(y0, 0.f); y1 = fmaxf(y1, 0.f);
                op[j] = __floats2half2_rn(y0, y1);
            }
            *(uint4*)&Xs[r * LDX + c] = outv;
        }
    } else {
        // fp32 X (layer 0, no BN)
        for (int idx = tid; idx < 4096; idx += 256) {
            int r = idx >> 5, c = (idx & 31) << 2;
            int gr = bm + r;
            float4 xv = make_float4(0.f, 0.f, 0.f, 0.f);
            if (gr < M) xv = *(const float4*)&Xf[(size_t)gr * FEAT + c];
            __half2 h0 = __floats2half2_rn(xv.x, xv.y);
            __half2 h1 = __floats2half2_rn(xv.z, xv.w);
            uint2 u; u.x = *(uint32_t*)&h0; u.y = *(uint32_t*)&h1;
            *(uint2*)&Xs[r * LDX + c] = u;
        }
    }
    __syncthreads();

    int warp = tid >> 5, lane = tid & 31;
    int m0 = warp * 16;

    float c_[16][4];
#pragma unroll
    for (int t = 0; t < 16; t++)
#pragma unroll
        for (int j = 0; j < 4; j++) c_[t][j] = 0.f;

    uint32_t sbase = smem_u32(smem);
    uint32_t xs_addr = sbase + ((m0 + (lane & 15)) * LDX + (lane >> 4) * 8) * 2;
    uint32_t ws_addr = sbase + (128 * LDX + (lane & 7) * LDX + ((lane >> 3) & 1) * 8) * 2;

#pragma unroll
    for (int k = 0; k < 8; k++) {
        uint32_t a0, a1, a2, a3;
        ldsm_x4(a0, a1, a2, a3, xs_addr + k * 32);
#pragma unroll
        for (int t = 0; t < 16; t++) {
            uint32_t b0, b1;
            ldsm_x2(b0, b1, ws_addr + (t * 8 * LDX) * 2 + k * 32);
            mma16816(c_[t], a0, a1, a2, a3, b0, b1);
        }
    }

    // ---- alpha epilogue
    int r0l = lane >> 2;
    int q = (lane & 3) * 2;
    float ps0 = 0.f, pd0 = 0.f, ps1 = 0.f, pd1 = 0.f;
#pragma unroll
    for (int t = 0; t < 16; t++) {
        int cA = t * 8 + q;
        float a0 = sAs[cA], a1 = sAs[cA + 1];
        float d0 = sAd[cA], d1 = sAd[cA + 1];
        ps0 += c_[t][0] * a0 + c_[t][1] * a1;
        pd0 += c_[t][0] * d0 + c_[t][1] * d1;
        ps1 += c_[t][2] * a0 + c_[t][3] * a1;
        pd1 += c_[t][2] * d0 + c_[t][3] * d1;
    }
#pragma unroll
    for (int o = 1; o < 4; o <<= 1) {
        ps0 += __shfl_xor_sync(0xffffffffu, ps0, o);
        pd0 += __shfl_xor_sync(0xffffffffu, pd0, o);
        ps1 += __shfl_xor_sync(0xffffffffu, ps1, o);
        pd1 += __shfl_xor_sync(0xffffffffu, pd1, o);
    }
    int gr0 = bm + m0 + r0l, gr1 = gr0 + 8;
    if ((lane & 3) == 0) {
        if (gr0 < M) { g_as[gr0] = ps0; g_ad[gr0] = pd0; }
        if (gr1 < M) { g_as[gr1] = ps1; g_ad[gr1] = pd1; }
    }

    // ---- stage C (fp16) into this warp's own Xs rows, then coalesced store
#pragma unroll
    for (int t = 0; t < 16; t++) {
        int colp = t * 8 + q;
        __half2 lo = __floats2half2_rn(c_[t][0], c_[t][1]);
        __half2 hi = __floats2half2_rn(c_[t][2], c_[t][3]);
        *(__half2*)&Xs[(m0 + r0l) * LDX + colp] = lo;
        *(__half2*)&Xs[(m0 + r0l + 8) * LDX + colp] = hi;
    }
    __syncwarp();
    for (int i = lane; i < 256; i += 32) {
        int r = i >> 4, ch = (i & 15) << 3;
        int gr = bm + m0 + r;
        if (gr < M)
            *(uint4*)&g_hh[(size_t)gr * FEAT + ch] = *(uint4*)&Xs[(m0 + r) * LDX + ch];
    }
}

__device__ __forceinline__ float leaky(float x) {
    return x >= 0.f ? x : NEG_SLOPE * x;
}

// ---------------- single-pass edge aggregation (warp per dst) ----------------
// Softmax without max-shift (logits bounded): out = (sum w_i h_i)/(sum w_i) + b
__global__ __launch_bounds__(256) void edge_kernel(const float* __restrict__ bias,
                                                   float* __restrict__ outf,   // fp32 (final layer)
                                                   __half* __restrict__ outh,  // fp16 (inter-layer)
                                                   float* __restrict__ bnsum,
                                                   float* __restrict__ bnsq,
                                                   int do_bn) {
    __shared__ float4 psum[8][32];
    __shared__ float4 psq[8][32];
    int tid = threadIdx.x, w = tid >> 5, lane = tid & 31;
    int d = blockIdx.x * 8 + w;            // grid = 12500 exactly
    int beg = g_rowptr[d], end = g_rowptr[d + 1];
    float ad = g_ad[d];

    float ax = 0.f, ay = 0.f, az = 0.f, aw = 0.f, wsum = 0.f;
    const uint2* h2 = (const uint2*)g_hh;
#pragma unroll 2
    for (int i = beg; i < end; i++) {
        int s = g_csrc[i];                        // broadcast load
        float wt = __expf(leaky(g_as[s] + ad));   // unnormalized
        wsum += wt;
        uint2 raw = h2[(size_t)s * 32 + lane];    // 8B/lane = 256B/edge
        float2 f0 = __half22float2(*(__half2*)&raw.x);
        float2 f1 = __half22float2(*(__half2*)&raw.y);
        ax += wt * f0.x; ay += wt * f0.y; az += wt * f1.x; aw += wt * f1.y;
    }
    float inv = 1.f / wsum;
    float4 bb = ((const float4*)bias)[lane];
    float4 o = make_float4(ax * inv + bb.x, ay * inv + bb.y,
                           az * inv + bb.z, aw * inv + bb.w);
    if (outf) {
        ((float4*)outf)[(size_t)d * 32 + lane] = o;
    } else {
        __half2 lo = __floats2half2_rn(o.x, o.y);
        __half2 hi = __floats2half2_rn(o.z, o.w);
        uint2 u; u.x = *(uint32_t*)&lo; u.y = *(uint32_t*)&hi;
        ((uint2*)outh)[(size_t)d * 32 + lane] = u;
    }

    if (do_bn) {
        psum[w][lane] = o;
        psq[w][lane]  = make_float4(o.x * o.x, o.y * o.y, o.z * o.z, o.w * o.w);
        __syncthreads();
        if (tid < FEAT) {
            float s = 0.f, q = 0.f;
            const float* ps = (const float*)psum;
            const float* pq = (const float*)psq;
#pragma unroll
            for (int ww = 0; ww < 8; ww++) {
                s += ps[ww * 128 + tid];
                q += pq[ww * 128 + tid];
            }
            atomicAdd(&bnsum[tid], s);
            atomicAdd(&bnsq[tid], q);
        }
    }
}

// ---------------- launch ----------------
extern "C" void kernel_launch(void* const* d_in, const int* in_sizes, int n_in,
                              void* d_out, int out_size) {
    const float* x  = (const float*)d_in[0];
    const int*   ei = (const int*)d_in[1];
    const float* W[3]  = {(const float*)d_in[2], (const float*)d_in[6],  (const float*)d_in[10]};
    const float* As[3] = {(const float*)d_in[3], (const float*)d_in[7],  (const float*)d_in[11]};
    const float* Ad[3] = {(const float*)d_in[4], (const float*)d_in[8],  (const float*)d_in[12]};
    const float* B[3]  = {(const float*)d_in[5], (const float*)d_in[9],  (const float*)d_in[13]};
    const float* gam[2] = {(const float*)d_in[14], (const float*)d_in[16]};
    const float* bet[2] = {(const float*)d_in[15], (const float*)d_in[17]};

    float *bs0, *bq0, *bs1, *bq1;
    int* cnt_ptr;
    __half *wh_ptr, *acch_ptr;
    cudaGetSymbolAddress((void**)&bs0, g_bnsum0);
    cudaGetSymbolAddress((void**)&bq0, g_bnsq0);
    cudaGetSymbolAddress((void**)&bs1, g_bnsum1);
    cudaGetSymbolAddress((void**)&bq1, g_bnsq1);
    cudaGetSymbolAddress((void**)&cnt_ptr, g_cnt);
    cudaGetSymbolAddress((void**)&wh_ptr, g_Wh);
    cudaGetSymbolAddress((void**)&acch_ptr, g_acch);

    const int SMEM_GEMM = (2 * 128 * LDX) * 2 + 4 * FEAT * 4;   // 71680 B
    cudaFuncSetAttribute(gemm_kernel,
                         cudaFuncAttributeMaxDynamicSharedMemorySize, SMEM_GEMM);

    cudaMemsetAsync(cnt_ptr, 0, NNODES * sizeof(int));

    // CSR build + weight convert (+BN zero)
    convw_kernel<<<(FEAT * FEAT + 255) / 256, 256>>>(W[0], W[1], W[2]);
    count_kernel<<<(NEDGES + 255) / 256, 256>>>(ei);
    scan1_kernel<<<SCAN_BLOCKS, 1024>>>();
    scan2_kernel<<<1, 128>>>();
    scan3_kernel<<<SCAN_BLOCKS, 1024>>>();
    scatter_kernel<<<(ETOT + 255) / 256, 256>>>(ei);

    const int gemm_grid = (NNODES + 127) / 128;   // 782
    const int edge_grid = NNODES / 8;             // 12500

    // layer 0 (fp32 X input, no BN)
    gemm_kernel<<<gemm_grid, 256, SMEM_GEMM>>>(x, nullptr, wh_ptr, As[0], Ad[0],
                                               nullptr, nullptr, nullptr, nullptr, 0, NNODES);
    edge_kernel<<<edge_grid, 256>>>(B[0], nullptr, acch_ptr, bs0, bq0, 1);
    // layer 1 (fp16 X, BN0+relu fused)
    gemm_kernel<<<gemm_grid, 256, SMEM_GEMM>>>(nullptr, acch_ptr, wh_ptr + FEAT * FEAT,
                                               As[1], Ad[1], gam[0], bet[0], bs0, bq0, 1, NNODES);
    edge_kernel<<<edge_grid, 256>>>(B[1], nullptr, acch_ptr, bs1, bq1, 1);
    // layer 2 (fp16 X, BN1+relu fused, fp32 output)
    gemm_kernel<<<gemm_grid, 256, SMEM_GEMM>>>(nullptr, acch_ptr, wh_ptr + 2 * FEAT * FEAT,
                                               As[2], Ad[2], gam[1], bet[1], bs1, bq1, 1, NNODES);
    edge_kernel<<<edge_grid, 256>>>(B[2], (float*)d_out, nullptr, nullptr, nullptr, 0);
}

// round 7
// speedup vs baseline: 3.1137x; 1.3534x over previous
#include <cuda_runtime.h>
#include <cuda_fp16.h>
#include <cstdint>

#define NNODES 100000
#define FEAT   128
#define NEDGES 1600000
#define ETOT   (NEDGES + NNODES)
#define BN_EPS 1e-5f
#define NEG_SLOPE 0.2f
#define LDX    136   // padded smem row pitch in halves (272B: conflict-free ldmatrix)
#define SCAN_BLOCKS ((NNODES + 1023) / 1024)   // 98

// ---------------- static device scratch ----------------
__device__ __half g_hh[(size_t)NNODES * FEAT];    // h of current layer (fp16)
__device__ __half g_acch[(size_t)NNODES * FEAT];  // inter-layer activation (fp16)
__device__ __half g_Wh[3][FEAT * FEAT];           // fp16 weights
__device__ float  g_as[NNODES];
__device__ float  g_ad[NNODES];
__device__ int    g_cnt[NNODES];
__device__ int    g_rowptr[NNODES + 1];
__device__ int    g_off[NNODES];
__device__ int    g_csrc[ETOT];
__device__ int    g_bsum[SCAN_BLOCKS];
__device__ float  g_bnsum0[FEAT], g_bnsq0[FEAT];
__device__ float  g_bnsum1[FEAT], g_bnsq1[FEAT];

// ---------------- weight convert + zero cnt/BN (grid covers NNODES) ----------------
__global__ void convw_kernel(const float* __restrict__ W0,
                             const float* __restrict__ W1,
                             const float* __restrict__ W2) {
    int i = blockIdx.x * blockDim.x + threadIdx.x;
    if (i < NNODES) g_cnt[i] = 0;
    if (i < FEAT) {
        g_bnsum0[i] = 0.f; g_bnsq0[i] = 0.f;
        g_bnsum1[i] = 0.f; g_bnsq1[i] = 0.f;
    }
    if (i < FEAT * FEAT) {
        g_Wh[0][i] = __float2half(W0[i]);
        g_Wh[1][i] = __float2half(W1[i]);
        g_Wh[2][i] = __float2half(W2[i]);
    }
}

__global__ void count_kernel(const int* __restrict__ ei) {
    int e = blockIdx.x * blockDim.x + threadIdx.x;
    if (e < NEDGES) atomicAdd(&g_cnt[ei[NEDGES + e]], 1);
}

// ---------------- scan phase 1: per-block inclusive scan of (cnt+1) ----------------
__global__ __launch_bounds__(1024) void scan1_kernel() {
    __shared__ int wsum[32];
    int tid = threadIdx.x, lane = tid & 31, wid = tid >> 5;
    int i = blockIdx.x * 1024 + tid;
    int v = (i < NNODES) ? g_cnt[i] + 1 : 0;   // +1 = self loop
    int s = v;
#pragma unroll
    for (int o = 1; o < 32; o <<= 1) {
        int t = __shfl_up_sync(0xffffffffu, s, o);
        if (lane >= o) s += t;
    }
    if (lane == 31) wsum[wid] = s;
    __syncthreads();
    if (wid == 0) {
        int ws = wsum[lane];
#pragma unroll
        for (int o = 1; o < 32; o <<= 1) {
            int t = __shfl_up_sync(0xffffffffu, ws, o);
            if (lane >= o) ws += t;
        }
        wsum[lane] = ws;
    }
    __syncthreads();
    int incl = s + (wid ? wsum[wid - 1] : 0);
    if (i < NNODES) g_rowptr[i + 1] = incl;
    if (tid == 1023) g_bsum[blockIdx.x] = incl;
}

// ---------------- scan phase 2+3 fused: each block computes its own carry ----------------
__global__ __launch_bounds__(1024) void scan23_kernel() {
    __shared__ int wred[32];
    int tid = threadIdx.x, lane = tid & 31, wid = tid >> 5;
    int v = (tid < SCAN_BLOCKS && tid < blockIdx.x) ? g_bsum[tid] : 0;
#pragma unroll
    for (int o = 16; o; o >>= 1) v += __shfl_xor_sync(0xffffffffu, v, o);
    if (lane == 0) wred[wid] = v;
    __syncthreads();
    if (wid == 0) {
        int t = wred[lane];
#pragma unroll
        for (int o = 16; o; o >>= 1) t += __shfl_xor_sync(0xffffffffu, t, o);
        if (lane == 0) wred[0] = t;
    }
    __syncthreads();
    int carry = wred[0];
    int i = blockIdx.x * 1024 + tid;
    if (i == 0) g_rowptr[0] = 0;
    if (i < NNODES) {
        int incl = g_rowptr[i + 1] + carry;
        g_rowptr[i + 1] = incl;
        g_off[i] = incl - (g_cnt[i] + 1);
    }
}

__global__ void scatter_kernel(const int* __restrict__ ei) {
    int idx = blockIdx.x * blockDim.x + threadIdx.x;
    if (idx >= ETOT) return;
    int s, d;
    if (idx < NEDGES) { s = ei[idx]; d = ei[NEDGES + idx]; }
    else { s = d = idx - NEDGES; }
    int p = atomicAdd(&g_off[d], 1);
    g_csrc[p] = s;
}

// ---------------- tensor-core helpers ----------------
__device__ __forceinline__ uint32_t smem_u32(const void* p) {
    uint32_t a;
    asm("{ .reg .u64 t; cvta.to.shared.u64 t, %1; cvt.u32.u64 %0, t; }"
        : "=r"(a) : "l"(p));
    return a;
}

__device__ __forceinline__ void ldsm_x4(uint32_t& a0, uint32_t& a1, uint32_t& a2,
                                        uint32_t& a3, uint32_t addr) {
    asm volatile("ldmatrix.sync.aligned.m8n8.x4.shared.b16 {%0,%1,%2,%3}, [%4];"
                 : "=r"(a0), "=r"(a1), "=r"(a2), "=r"(a3) : "r"(addr));
}

__device__ __forceinline__ void ldsm_x2(uint32_t& b0, uint32_t& b1, uint32_t addr) {
    asm volatile("ldmatrix.sync.aligned.m8n8.x2.shared.b16 {%0,%1}, [%2];"
                 : "=r"(b0), "=r"(b1) : "r"(addr));
}

__device__ __forceinline__ void mma16816(float c[4], uint32_t a0, uint32_t a1,
                                         uint32_t a2, uint32_t a3,
                                         uint32_t b0, uint32_t b1) {
    asm volatile(
        "mma.sync.aligned.m16n8k16.row.col.f32.f16.f16.f32 "
        "{%0,%1,%2,%3}, {%4,%5,%6,%7}, {%8,%9}, {%0,%1,%2,%3};"
        : "+f"(c[0]), "+f"(c[1]), "+f"(c[2]), "+f"(c[3])
        : "r"(a0), "r"(a1), "r"(a2), "r"(a3), "r"(b0), "r"(b1));
}

// ---------------- GEMM (HMMA) + fused BN-on-load + alpha epilogue ----------------
__global__ __launch_bounds__(256) void gemm_kernel(
    const float* __restrict__ Xf, const __half* __restrict__ Xh,
    const __half* __restrict__ Wh,
    const float* __restrict__ asrc, const float* __restrict__ adst,
    const float* __restrict__ gamma, const float* __restrict__ beta,
    const float* __restrict__ bsum, const float* __restrict__ bsq,
    int use_bn, int M) {
    extern __shared__ __half smem[];
    __half* Xs = smem;                       // [128][LDX]
    __half* Ws = smem + 128 * LDX;           // [128][LDX]
    float* sc  = (float*)(smem + 2 * 128 * LDX);
    float* sh  = sc + FEAT;
    float* sAs = sh + FEAT;
    float* sAd = sAs + FEAT;

    int tid = threadIdx.x;
    int bm = blockIdx.x * 128;

    if (tid < FEAT) {
        sAs[tid] = asrc[tid];
        sAd[tid] = adst[tid];
        if (use_bn) {
            const float invN = 1.f / (float)NNODES;
            float mu = bsum[tid] * invN;
            float var = bsq[tid] * invN - mu * mu;
            float s = gamma[tid] * rsqrtf(var + BN_EPS);
            sc[tid] = s;
            sh[tid] = beta[tid] - mu * s;
        } else { sc[tid] = 1.f; sh[tid] = 0.f; }
    }
    __syncthreads();

    for (int idx = tid; idx < 2048; idx += 256) {
        int r = idx >> 4, c = (idx & 15) << 3;
        *(uint4*)&Ws[r * LDX + c] = *(const uint4*)&Wh[r * FEAT + c];
    }
    if (Xh) {
        for (int idx = tid; idx < 2048; idx += 256) {
            int r = idx >> 4, c = (idx & 15) << 3;
            int gr = bm + r;
            uint4 u = make_uint4(0u, 0u, 0u, 0u);
            if (gr < M) u = *(const uint4*)&Xh[(size_t)gr * FEAT + c];
            __half2* hp = (__half2*)&u;
            uint4 outv;
            __half2* op = (__half2*)&outv;
#pragma unroll
            for (int j = 0; j < 4; j++) {
                float2 f = __half22float2(hp[j]);
                int cc = c + j * 2;
                float y0 = f.x * sc[cc] + sh[cc];
                float y1 = f.y * sc[cc + 1] + sh[cc + 1];
                y0 = fmaxf(y0, 0.f); y1 = fmaxf(y1, 0.f);
                op[j] = __floats2half2_rn(y0, y1);
            }
            *(uint4*)&Xs[r * LDX + c] = outv;
        }
    } else {
        for (int idx = tid; idx < 4096; idx += 256) {
            int r = idx >> 5, c = (idx & 31) << 2;
            int gr = bm + r;
            float4 xv = make_float4(0.f, 0.f, 0.f, 0.f);
            if (gr < M) xv = *(const float4*)&Xf[(size_t)gr * FEAT + c];
            __half2 h0 = __floats2half2_rn(xv.x, xv.y);
            __half2 h1 = __floats2half2_rn(xv.z, xv.w);
            uint2 u; u.x = *(uint32_t*)&h0; u.y = *(uint32_t*)&h1;
            *(uint2*)&Xs[r * LDX + c] = u;
        }
    }
    __syncthreads();

    int warp = tid >> 5, lane = tid & 31;
    int m0 = warp * 16;

    float c_[16][4];
#pragma unroll
    for (int t = 0; t < 16; t++)
#pragma unroll
        for (int j = 0; j < 4; j++) c_[t][j] = 0.f;

    uint32_t sbase = smem_u32(smem);
    uint32_t xs_addr = sbase + ((m0 + (lane & 15)) * LDX + (lane >> 4) * 8) * 2;
    uint32_t ws_addr = sbase + (128 * LDX + (lane & 7) * LDX + ((lane >> 3) & 1) * 8) * 2;

#pragma unroll
    for (int k = 0; k < 8; k++) {
        uint32_t a0, a1, a2, a3;
        ldsm_x4(a0, a1, a2, a3, xs_addr + k * 32);
#pragma unroll
        for (int t = 0; t < 16; t++) {
            uint32_t b0, b1;
            ldsm_x2(b0, b1, ws_addr + (t * 8 * LDX) * 2 + k * 32);
            mma16816(c_[t], a0, a1, a2, a3, b0, b1);
        }
    }

    // ---- alpha epilogue
    int r0l = lane >> 2;
    int q = (lane & 3) * 2;
    float ps0 = 0.f, pd0 = 0.f, ps1 = 0.f, pd1 = 0.f;
#pragma unroll
    for (int t = 0; t < 16; t++) {
        int cA = t * 8 + q;
        float a0 = sAs[cA], a1 = sAs[cA + 1];
        float d0 = sAd[cA], d1 = sAd[cA + 1];
        ps0 += c_[t][0] * a0 + c_[t][1] * a1;
        pd0 += c_[t][0] * d0 + c_[t][1] * d1;
        ps1 += c_[t][2] * a0 + c_[t][3] * a1;
        pd1 += c_[t][2] * d0 + c_[t][3] * d1;
    }
#pragma unroll
    for (int o = 1; o < 4; o <<= 1) {
        ps0 += __shfl_xor_sync(0xffffffffu, ps0, o);
        pd0 += __shfl_xor_sync(0xffffffffu, pd0, o);
        ps1 += __shfl_xor_sync(0xffffffffu, ps1, o);
        pd1 += __shfl_xor_sync(0xffffffffu, pd1, o);
    }
    int gr0 = bm + m0 + r0l, gr1 = gr0 + 8;
    if ((lane & 3) == 0) {
        if (gr0 < M) { g_as[gr0] = ps0; g_ad[gr0] = pd0; }
        if (gr1 < M) { g_as[gr1] = ps1; g_ad[gr1] = pd1; }
    }

    // ---- stage C (fp16) into this warp's own Xs rows, then coalesced store
#pragma unroll
    for (int t = 0; t < 16; t++) {
        int colp = t * 8 + q;
        __half2 lo = __floats2half2_rn(c_[t][0], c_[t][1]);
        __half2 hi = __floats2half2_rn(c_[t][2], c_[t][3]);
        *(__half2*)&Xs[(m0 + r0l) * LDX + colp] = lo;
        *(__half2*)&Xs[(m0 + r0l + 8) * LDX + colp] = hi;
    }
    __syncwarp();
    for (int i = lane; i < 256; i += 32) {
        int r = i >> 4, ch = (i & 15) << 3;
        int gr = bm + m0 + r;
        if (gr < M)
            *(uint4*)&g_hh[(size_t)gr * FEAT + ch] = *(uint4*)&Xs[(m0 + r) * LDX + ch];
    }
}

__device__ __forceinline__ float leaky(float x) {
    return x >= 0.f ? x : NEG_SLOPE * x;
}

// ---------------- single-pass edge aggregation: half-warp per edge ----------------
__global__ __launch_bounds__(256) void edge_kernel(const float* __restrict__ bias,
                                                   float* __restrict__ outf,
                                                   __half* __restrict__ outh,
                                                   float* __restrict__ bnsum,
                                                   float* __restrict__ bnsq,
                                                   int do_bn) {
    __shared__ float psum[8][128];
    __shared__ float psq[8][128];
    int tid = threadIdx.x, w = tid >> 5, lane = tid & 31;
    int half = lane >> 4, hl = lane & 15;
    int d = blockIdx.x * 8 + w;            // grid = 12500 exactly
    int beg = g_rowptr[d], end = g_rowptr[d + 1];
    float ad = g_ad[d];

    float acc[8];
#pragma unroll
    for (int j = 0; j < 8; j++) acc[j] = 0.f;
    float wsum = 0.f;

    const uint4* h4 = (const uint4*)g_hh;   // 16 uint4 per node row
#pragma unroll 2
    for (int i = beg; i < end; i += 2) {
        int e = i + half;
        bool valid = e < end;
        int s = g_csrc[valid ? e : end - 1];
        float wt = valid ? __expf(leaky(g_as[s] + ad)) : 0.f;
        wsum += wt;
        uint4 raw = h4[(size_t)s * 16 + hl];   // 16B/lane: 16 lanes cover 256B edge
        __half2* hp = (__half2*)&raw;
#pragma unroll
        for (int j = 0; j < 4; j++) {
            float2 f = __half22float2(hp[j]);
            acc[2 * j]     += wt * f.x;
            acc[2 * j + 1] += wt * f.y;
        }
    }
    // combine halves: lanes 0-15 <- + lanes 16-31
#pragma unroll
    for (int j = 0; j < 8; j++)
        acc[j] += __shfl_down_sync(0xffffffffu, acc[j], 16);
    wsum += __shfl_down_sync(0xffffffffu, wsum, 16);

    if (half == 0) {
        float inv = 1.f / wsum;
        float4 b0 = ((const float4*)bias)[hl * 2];
        float4 b1 = ((const float4*)bias)[hl * 2 + 1];
        float o[8];
        o[0] = acc[0] * inv + b0.x; o[1] = acc[1] * inv + b0.y;
        o[2] = acc[2] * inv + b0.z; o[3] = acc[3] * inv + b0.w;
        o[4] = acc[4] * inv + b1.x; o[5] = acc[5] * inv + b1.y;
        o[6] = acc[6] * inv + b1.z; o[7] = acc[7] * inv + b1.w;
        if (outf) {
            ((float4*)outf)[(size_t)d * 32 + hl * 2]     = make_float4(o[0], o[1], o[2], o[3]);
            ((float4*)outf)[(size_t)d * 32 + hl * 2 + 1] = make_float4(o[4], o[5], o[6], o[7]);
        } else {
            __half2 q0 = __floats2half2_rn(o[0], o[1]);
            __half2 q1 = __floats2half2_rn(o[2], o[3]);
            __half2 q2 = __floats2half2_rn(o[4], o[5]);
            __half2 q3 = __floats2half2_rn(o[6], o[7]);
            uint4 u;
            u.x = *(uint32_t*)&q0; u.y = *(uint32_t*)&q1;
            u.z = *(uint32_t*)&q2; u.w = *(uint32_t*)&q3;
            ((uint4*)outh)[(size_t)d * 16 + hl] = u;
        }
        if (do_bn) {
            *(float4*)&psum[w][hl * 8]     = make_float4(o[0], o[1], o[2], o[3]);
            *(float4*)&psum[w][hl * 8 + 4] = make_float4(o[4], o[5], o[6], o[7]);
            *(float4*)&psq[w][hl * 8]      = make_float4(o[0]*o[0], o[1]*o[1], o[2]*o[2], o[3]*o[3]);
            *(float4*)&psq[w][hl * 8 + 4]  = make_float4(o[4]*o[4], o[5]*o[5], o[6]*o[6], o[7]*o[7]);
        }
    }

    if (do_bn) {
        __syncthreads();
        if (tid < FEAT) {
            float s = 0.f, q = 0.f;
#pragma unroll
            for (int ww = 0; ww < 8; ww++) {
                s += psum[ww][tid];
                q += psq[ww][tid];
            }
            atomicAdd(&bnsum[tid], s);
            atomicAdd(&bnsq[tid], q);
        }
    }
}

// ---------------- launch ----------------
extern "C" void kernel_launch(void* const* d_in, const int* in_sizes, int n_in,
                              void* d_out, int out_size) {
    const float* x  = (const float*)d_in[0];
    const int*   ei = (const int*)d_in[1];
    const float* W[3]  = {(const float*)d_in[2], (const float*)d_in[6],  (const float*)d_in[10]};
    const float* As[3] = {(const float*)d_in[3], (const float*)d_in[7],  (const float*)d_in[11]};
    const float* Ad[3] = {(const float*)d_in[4], (const float*)d_in[8],  (const float*)d_in[12]};
    const float* B[3]  = {(const float*)d_in[5], (const float*)d_in[9],  (const float*)d_in[13]};
    const float* gam[2] = {(const float*)d_in[14], (const float*)d_in[16]};
    const float* bet[2] = {(const float*)d_in[15], (const float*)d_in[17]};

    float *bs0, *bq0, *bs1, *bq1;
    __half *wh_ptr, *acch_ptr;
    cudaGetSymbolAddress((void**)&bs0, g_bnsum0);
    cudaGetSymbolAddress((void**)&bq0, g_bnsq0);
    cudaGetSymbolAddress((void**)&bs1, g_bnsum1);
    cudaGetSymbolAddress((void**)&bq1, g_bnsq1);
    cudaGetSymbolAddress((void**)&wh_ptr, g_Wh);
    cudaGetSymbolAddress((void**)&acch_ptr, g_acch);

    const int SMEM_GEMM = (2 * 128 * LDX) * 2 + 4 * FEAT * 4;   // 71680 B
    cudaFuncSetAttribute(gemm_kernel,
                         cudaFuncAttributeMaxDynamicSharedMemorySize, SMEM_GEMM);

    // CSR build (5 launches; gemm0 is launch #6 for ncu -s 5 -c 1)
    convw_kernel<<<(NNODES + 255) / 256, 256>>>(W[0], W[1], W[2]);
    count_kernel<<<(NEDGES + 255) / 256, 256>>>(ei);
    scan1_kernel<<<SCAN_BLOCKS, 1024>>>();
    scan23_kernel<<<SCAN_BLOCKS, 1024>>>();
    scatter_kernel<<<(ETOT + 255) / 256, 256>>>(ei);

    const int gemm_grid = (NNODES + 127) / 128;   // 782
    const int edge_grid = NNODES / 8;             // 12500

    // layer 0 (fp32 X input, no BN)
    gemm_kernel<<<gemm_grid, 256, SMEM_GEMM>>>(x, nullptr, wh_ptr, As[0], Ad[0],
                                               nullptr, nullptr, nullptr, nullptr, 0, NNODES);
    edge_kernel<<<edge_grid, 256>>>(B[0], nullptr, acch_ptr, bs0, bq0, 1);
    // layer 1 (fp16 X, BN0+relu fused)
    gemm_kernel<<<gemm_grid, 256, SMEM_GEMM>>>(nullptr, acch_ptr, wh_ptr + FEAT * FEAT,
                                               As[1], Ad[1], gam[0], bet[0], bs0, bq0, 1, NNODES);
    edge_kernel<<<edge_grid, 256>>>(B[1], nullptr, acch_ptr, bs1, bq1, 1);
    // layer 2 (fp16 X, BN1+relu fused, fp32 output)
    gemm_kernel<<<gemm_grid, 256, SMEM_GEMM>>>(nullptr, acch_ptr, wh_ptr + 2 * FEAT * FEAT,
                                               As[2], Ad[2], gam[1], bet[1], bs1, bq1, 1, NNODES);
    edge_kernel<<<edge_grid, 256>>>(B[2], (float*)d_out, nullptr, nullptr, nullptr, 0);
}